// round 1
// baseline (speedup 1.0000x reference)
#include <cuda_runtime.h>
#include <cuda_bf16.h>
#include <cstdint>

// Problem constants
#define BB   1024    // batch
#define AN   256     // actions per row
#define DD   256     // emb dim
#define HD   512     // history dim
#define AD   512     // action dim (2*DD)
#define KIN  1024    // 2*DD + HD
#define NRR  400     // num relations
#define HUGEV 1e31f

// Scratch (device globals; no allocation allowed)
__device__ float g_X [BB * AD];        // relu(W1 [E;H;Q] + b1)
__device__ float g_X2[BB * AD];        // X @ W2 + b2
__device__ float g_RP[BB * NRR];       // X2[:, :256] @ rel_emb^T

// ---------------------------------------------------------------------------
// GEMM1: X[b, n] = relu( sum_k concat(E,H,Q)[b,k] * W1[k,n] + b1[n] )
// M=1024, K=1024, N=512. 64x64 tile, BK=16, 256 threads, 4x4 micro-tile.
// A-row gather fused into the tile load.
// ---------------------------------------------------------------------------
__global__ void k_gemm1(const int* __restrict__ e, const int* __restrict__ q,
                        const float* __restrict__ hstate,
                        const float* __restrict__ ent_emb,
                        const float* __restrict__ rel_emb,
                        const float* __restrict__ W1,
                        const float* __restrict__ b1)
{
    const int K = KIN, N = AD;
    __shared__ float As[16][65];
    __shared__ float Bs[16][64];

    int n0 = blockIdx.x * 64;
    int m0 = blockIdx.y * 64;
    int t  = threadIdx.x;
    int tx = t & 15, ty = t >> 4;

    float acc[4][4] = {};

    for (int k0 = 0; k0 < K; k0 += 16) {
        // Load A tile (64 rows x 16 cols) with concat gather.
        // k-tile of 16 never straddles a segment boundary (256/768 are mult of 16).
        #pragma unroll
        for (int i = 0; i < 4; i++) {
            int lin = t + i * 256;
            int r = lin >> 4, c = lin & 15;
            int brow = m0 + r;
            int gk = k0 + c;
            float v;
            if (gk < DD) {
                v = ent_emb[(size_t)e[brow] * DD + gk];
            } else if (gk < DD + HD) {
                v = hstate[(size_t)brow * HD + (gk - DD)];
            } else {
                v = rel_emb[(size_t)q[brow] * DD + (gk - DD - HD)];
            }
            As[c][r] = v;
        }
        // Load B tile (16 x 64), coalesced
        #pragma unroll
        for (int i = 0; i < 4; i++) {
            int lin = t + i * 256;
            int r = lin >> 6, c = lin & 63;
            Bs[r][c] = W1[(size_t)(k0 + r) * N + n0 + c];
        }
        __syncthreads();

        #pragma unroll
        for (int kk = 0; kk < 16; kk++) {
            float a[4], b[4];
            #pragma unroll
            for (int i = 0; i < 4; i++) a[i] = As[kk][ty * 4 + i];
            #pragma unroll
            for (int j = 0; j < 4; j++) b[j] = Bs[kk][tx * 4 + j];
            #pragma unroll
            for (int i = 0; i < 4; i++)
                #pragma unroll
                for (int j = 0; j < 4; j++)
                    acc[i][j] = fmaf(a[i], b[j], acc[i][j]);
        }
        __syncthreads();
    }

    #pragma unroll
    for (int i = 0; i < 4; i++) {
        int m = m0 + ty * 4 + i;
        #pragma unroll
        for (int j = 0; j < 4; j++) {
            int n = n0 + tx * 4 + j;
            float v = acc[i][j] + b1[n];
            g_X[(size_t)m * N + n] = fmaxf(v, 0.0f);
        }
    }
}

// ---------------------------------------------------------------------------
// GEMM2: X2 = X @ W2 + b2.  M=1024, K=512, N=512.
// ---------------------------------------------------------------------------
__global__ void k_gemm2(const float* __restrict__ W2, const float* __restrict__ b2)
{
    const int K = AD, N = AD;
    __shared__ float As[16][65];
    __shared__ float Bs[16][64];

    int n0 = blockIdx.x * 64;
    int m0 = blockIdx.y * 64;
    int t  = threadIdx.x;
    int tx = t & 15, ty = t >> 4;

    float acc[4][4] = {};

    for (int k0 = 0; k0 < K; k0 += 16) {
        #pragma unroll
        for (int i = 0; i < 4; i++) {
            int lin = t + i * 256;
            int r = lin >> 4, c = lin & 15;
            As[c][r] = g_X[(size_t)(m0 + r) * K + k0 + c];
        }
        #pragma unroll
        for (int i = 0; i < 4; i++) {
            int lin = t + i * 256;
            int r = lin >> 6, c = lin & 63;
            Bs[r][c] = W2[(size_t)(k0 + r) * N + n0 + c];
        }
        __syncthreads();

        #pragma unroll
        for (int kk = 0; kk < 16; kk++) {
            float a[4], b[4];
            #pragma unroll
            for (int i = 0; i < 4; i++) a[i] = As[kk][ty * 4 + i];
            #pragma unroll
            for (int j = 0; j < 4; j++) b[j] = Bs[kk][tx * 4 + j];
            #pragma unroll
            for (int i = 0; i < 4; i++)
                #pragma unroll
                for (int j = 0; j < 4; j++)
                    acc[i][j] = fmaf(a[i], b[j], acc[i][j]);
        }
        __syncthreads();
    }

    #pragma unroll
    for (int i = 0; i < 4; i++) {
        int m = m0 + ty * 4 + i;
        #pragma unroll
        for (int j = 0; j < 4; j++) {
            int n = n0 + tx * 4 + j;
            g_X2[(size_t)m * N + n] = acc[i][j] + b2[n];
        }
    }
}

// ---------------------------------------------------------------------------
// GEMM3: R_proj[b, r] = sum_k X2[b, k] * rel_emb[r, k]   (k < 256)
// M=1024, N=400, K=256. B-operand access is strided (transposed) but the
// relation table is 409KB -> L2-resident; cost negligible.
// ---------------------------------------------------------------------------
__global__ void k_relproj(const float* __restrict__ rel_emb)
{
    const int K = DD, N = NRR;
    __shared__ float As[16][65];
    __shared__ float Bs[16][64];

    int n0 = blockIdx.x * 64;
    int m0 = blockIdx.y * 64;
    int t  = threadIdx.x;
    int tx = t & 15, ty = t >> 4;

    float acc[4][4] = {};

    for (int k0 = 0; k0 < K; k0 += 16) {
        #pragma unroll
        for (int i = 0; i < 4; i++) {
            int lin = t + i * 256;
            int r = lin >> 4, c = lin & 15;
            As[c][r] = g_X2[(size_t)(m0 + r) * AD + k0 + c];   // first 256 cols of X2
        }
        #pragma unroll
        for (int i = 0; i < 4; i++) {
            int lin = t + i * 256;
            int r = lin >> 6, c = lin & 63;
            int n = n0 + c;
            Bs[r][c] = (n < N) ? rel_emb[(size_t)n * DD + k0 + r] : 0.0f;
        }
        __syncthreads();

        #pragma unroll
        for (int kk = 0; kk < 16; kk++) {
            float a[4], b[4];
            #pragma unroll
            for (int i = 0; i < 4; i++) a[i] = As[kk][ty * 4 + i];
            #pragma unroll
            for (int j = 0; j < 4; j++) b[j] = Bs[kk][tx * 4 + j];
            #pragma unroll
            for (int i = 0; i < 4; i++)
                #pragma unroll
                for (int j = 0; j < 4; j++)
                    acc[i][j] = fmaf(a[i], b[j], acc[i][j]);
        }
        __syncthreads();
    }

    #pragma unroll
    for (int i = 0; i < 4; i++) {
        int m = m0 + ty * 4 + i;
        #pragma unroll
        for (int j = 0; j < 4; j++) {
            int n = n0 + tx * 4 + j;
            if (n < N) g_RP[(size_t)m * N + n] = acc[i][j];
        }
    }
}

// ---------------------------------------------------------------------------
// Scores + masked softmax + entropy. One block per batch row, 256 threads.
// score[b,a] = RP[b, r_space[b,a]] + ent_emb[e_space[b,a]] . X2[b, 256:512]
//              - (1 - mask) * HUGE
// ---------------------------------------------------------------------------
__global__ void k_scores(const int*   __restrict__ r_space,
                         const int*   __restrict__ e_space,
                         const float* __restrict__ mask,
                         const float* __restrict__ ent_emb,
                         float* __restrict__ dist,
                         float* __restrict__ entropy)
{
    int b = blockIdx.x;
    int t = threadIdx.x;
    int warp = t >> 5, lane = t & 31;

    __shared__ __align__(16) float x2b[DD];     // second half of X2 row
    __shared__ float rp[NRR];
    __shared__ float sc[AN];
    __shared__ float red[8];

    x2b[t] = g_X2[(size_t)b * AD + DD + t];
    for (int i = t; i < NRR; i += 256) rp[i] = g_RP[(size_t)b * NRR + i];
    __syncthreads();

    const float4* xp = reinterpret_cast<const float4*>(x2b);
    float4 xv0 = xp[lane * 2 + 0];
    float4 xv1 = xp[lane * 2 + 1];

    // 8 warps, one action per warp per iteration
    for (int a = warp; a < AN; a += 8) {
        int ie = e_space[b * AN + a];
        const float4* ep = reinterpret_cast<const float4*>(ent_emb + (size_t)ie * DD);
        float4 v0 = ep[lane * 2 + 0];
        float4 v1 = ep[lane * 2 + 1];
        float s = v0.x * xv0.x + v0.y * xv0.y + v0.z * xv0.z + v0.w * xv0.w
                + v1.x * xv1.x + v1.y * xv1.y + v1.z * xv1.z + v1.w * xv1.w;
        #pragma unroll
        for (int o = 16; o > 0; o >>= 1) s += __shfl_xor_sync(0xFFFFFFFFu, s, o);
        if (lane == 0) {
            int ir = r_space[b * AN + a];
            float m = mask[b * AN + a];
            sc[a] = s + rp[ir] - (1.0f - m) * HUGEV;
        }
    }
    __syncthreads();

    // softmax over 256 elements (one per thread)
    float s = sc[t];

    // max reduce
    float mx = s;
    #pragma unroll
    for (int o = 16; o > 0; o >>= 1) mx = fmaxf(mx, __shfl_xor_sync(0xFFFFFFFFu, mx, o));
    if (lane == 0) red[warp] = mx;
    __syncthreads();
    if (t < 8) {
        float v = red[t];
        #pragma unroll
        for (int o = 4; o > 0; o >>= 1) v = fmaxf(v, __shfl_xor_sync(0xFFu, v, o));
        if (t == 0) red[0] = v;
    }
    __syncthreads();
    mx = red[0];

    float ex = expf(s - mx);

    // sum reduce
    float sm = ex;
    #pragma unroll
    for (int o = 16; o > 0; o >>= 1) sm += __shfl_xor_sync(0xFFFFFFFFu, sm, o);
    __syncthreads();
    if (lane == 0) red[warp] = sm;
    __syncthreads();
    if (t < 8) {
        float v = red[t];
        #pragma unroll
        for (int o = 4; o > 0; o >>= 1) v += __shfl_xor_sync(0xFFu, v, o);
        if (t == 0) red[0] = v;
    }
    __syncthreads();
    float total = red[0];

    float p = ex / total;
    dist[(size_t)b * AN + t] = p;

    // entropy: -sum p * log(max(p, 1e-20)); p==0 contributes exactly 0
    float term = p * logf(fmaxf(p, 1e-20f));
    float es = term;
    #pragma unroll
    for (int o = 16; o > 0; o >>= 1) es += __shfl_xor_sync(0xFFFFFFFFu, es, o);
    __syncthreads();
    if (lane == 0) red[warp] = es;
    __syncthreads();
    if (t < 8) {
        float v = red[t];
        #pragma unroll
        for (int o = 4; o > 0; o >>= 1) v += __shfl_xor_sync(0xFFu, v, o);
        if (t == 0) entropy[b] = -v;
    }
}

// ---------------------------------------------------------------------------
// Launch
// ---------------------------------------------------------------------------
extern "C" void kernel_launch(void* const* d_in, const int* in_sizes, int n_in,
                              void* d_out, int out_size)
{
    const int*   e        = (const int*)  d_in[0];
    const int*   q        = (const int*)  d_in[1];
    const float* hstate   = (const float*)d_in[2];
    const int*   r_space  = (const int*)  d_in[3];
    const int*   e_space  = (const int*)  d_in[4];
    const float* amask    = (const float*)d_in[5];
    const float* ent_emb  = (const float*)d_in[6];
    const float* rel_emb  = (const float*)d_in[7];
    const float* W1       = (const float*)d_in[8];
    const float* b1       = (const float*)d_in[9];
    const float* W2       = (const float*)d_in[10];
    const float* b2       = (const float*)d_in[11];

    float* dist    = (float*)d_out;              // [B, AN]
    float* entropy = (float*)d_out + (size_t)BB * AN;  // [B]

    dim3 g1(AD / 64, BB / 64);                   // (8, 16)
    k_gemm1<<<g1, 256>>>(e, q, hstate, ent_emb, rel_emb, W1, b1);

    dim3 g2(AD / 64, BB / 64);                   // (8, 16)
    k_gemm2<<<g2, 256>>>(W2, b2);

    dim3 g3((NRR + 63) / 64, BB / 64);           // (7, 16)
    k_relproj<<<g3, 256>>>(rel_emb);

    k_scores<<<BB, 256>>>(r_space, e_space, amask, ent_emb, dist, entropy);
}

// round 2
// speedup vs baseline: 1.5543x; 1.5543x over previous
#include <cuda_runtime.h>
#include <cuda_bf16.h>
#include <cstdint>

#define BB   1024
#define AN   256
#define DD   256
#define HD   512
#define AD   512
#define KIN  1024
#define NRR  400
#define NF   912     // AD + NRR fused N
#define HUGEV 1e31f

// Scratch
__device__ float g_X [BB * AD];         // relu(W1 [E;H;Q] + b1)
__device__ float g_X2[BB * AD];         // X @ W2 + b2
__device__ float g_RP[BB * NRR];        // X2[:, :256] @ rel_emb^T  (via Wr)
__device__ float g_Wr[AD * NRR];        // W2[:, :256] @ rel_emb^T   [512,400]
__device__ float g_br[NRR];             // b2[:256] @ rel_emb^T

// ---------------------------------------------------------------------------
// Shared compute macro: 64x64 tile, BK=16, 256 threads, 4x4 microtile,
// all smem reads are LDS.128, double-buffered.
// ---------------------------------------------------------------------------
#define COMPUTE_TILE(buf)                                                    \
    _Pragma("unroll")                                                        \
    for (int kk = 0; kk < 16; kk++) {                                        \
        float4 av = *(const float4*)&As[buf][kk][ty * 4];                    \
        float4 bv = *(const float4*)&Bs[buf][kk][tx * 4];                    \
        float a_[4] = {av.x, av.y, av.z, av.w};                              \
        float b_[4] = {bv.x, bv.y, bv.z, bv.w};                              \
        _Pragma("unroll")                                                    \
        for (int i = 0; i < 4; i++)                                          \
            _Pragma("unroll")                                                \
            for (int j = 0; j < 4; j++)                                      \
                acc[i][j] = fmaf(a_[i], b_[j], acc[i][j]);                   \
    }

// ---------------------------------------------------------------------------
// GEMM1: X = relu(concat(E,H,Q) @ W1 + b1).  M=1024 K=1024 N=512.
// ---------------------------------------------------------------------------
__global__ void k_gemm1(const int* __restrict__ e, const int* __restrict__ q,
                        const float* __restrict__ hstate,
                        const float* __restrict__ ent_emb,
                        const float* __restrict__ rel_emb,
                        const float* __restrict__ W1,
                        const float* __restrict__ b1)
{
    __shared__ float As[2][16][64];
    __shared__ float Bs[2][16][64];

    const int N = AD;
    int n0 = blockIdx.x * 64, m0 = blockIdx.y * 64;
    int t  = threadIdx.x;
    int tx = t & 15, ty = t >> 4;

    // A load mapping: row lm (0..63), k offset lkc in {0,4,8,12}
    int lm  = t >> 2;
    int lkc = (t & 3) * 4;
    int brow = m0 + lm;
    int ei = e[brow], qi = q[brow];
    const float* arow0 = ent_emb + (size_t)ei * DD;                 // k in [0,256)
    const float* arow1 = hstate + (size_t)brow * HD - DD;           // k in [256,768)
    const float* arow2 = rel_emb + (size_t)qi * DD - (DD + HD);     // k in [768,1024)

    // B load mapping: Bs[t>>4][(t&15)*4]
    int brr = t >> 4;
    int bcc = (t & 15) * 4;

    float acc[4][4] = {};

    auto loadA = [&](int k0) -> float4 {
        int gk = k0 + lkc;
        const float* p = (gk < DD) ? (arow0 + gk)
                        : (gk < DD + HD) ? (arow1 + gk) : (arow2 + gk);
        return *(const float4*)p;
    };
    auto loadB = [&](int k0) -> float4 {
        return *(const float4*)&W1[(size_t)(k0 + brr) * N + n0 + bcc];
    };

    const int NT = KIN / 16;
    float4 ar = loadA(0), brv = loadB(0);
    {   // store stage 0
        As[0][lkc + 0][lm] = ar.x; As[0][lkc + 1][lm] = ar.y;
        As[0][lkc + 2][lm] = ar.z; As[0][lkc + 3][lm] = ar.w;
        *(float4*)&Bs[0][brr][bcc] = brv;
    }
    __syncthreads();

    int buf = 0;
    for (int it = 0; it < NT; it++) {
        float4 an, bn;
        if (it + 1 < NT) { an = loadA((it + 1) * 16); bn = loadB((it + 1) * 16); }
        COMPUTE_TILE(buf);
        if (it + 1 < NT) {
            int nb = buf ^ 1;
            As[nb][lkc + 0][lm] = an.x; As[nb][lkc + 1][lm] = an.y;
            As[nb][lkc + 2][lm] = an.z; As[nb][lkc + 3][lm] = an.w;
            *(float4*)&Bs[nb][brr][bcc] = bn;
            __syncthreads();
            buf = nb;
        }
    }

    #pragma unroll
    for (int i = 0; i < 4; i++) {
        int m = m0 + ty * 4 + i;
        #pragma unroll
        for (int j = 0; j < 4; j++) {
            int n = n0 + tx * 4 + j;
            g_X[(size_t)m * N + n] = fmaxf(acc[i][j] + b1[n], 0.0f);
        }
    }
}

// ---------------------------------------------------------------------------
// Wr = W2[:, :256] @ rel_emb^T.  M=512(k-rows) N=400(relations) K=256.
// A[m][j] = W2[m*512 + j]; B[j][r] = rel_emb[r*256 + j] (both loaded k-major).
// ---------------------------------------------------------------------------
__global__ void k_wr(const float* __restrict__ W2, const float* __restrict__ rel_emb)
{
    __shared__ float As[2][16][64];
    __shared__ float Bs[2][16][64];

    int n0 = blockIdx.x * 64, m0 = blockIdx.y * 64;
    int t  = threadIdx.x;
    int tx = t & 15, ty = t >> 4;

    int lm  = t >> 2;
    int lkc = (t & 3) * 4;
    const float* arow = W2 + (size_t)(m0 + lm) * AD;        // j-contiguous
    int rrow = n0 + lm;                                     // relation index for B load
    bool rvalid = rrow < NRR;
    const float* brow_p = rel_emb + (size_t)(rvalid ? rrow : 0) * DD;

    float acc[4][4] = {};
    const int NT = DD / 16;

    auto loadA = [&](int k0) -> float4 { return *(const float4*)(arow + k0 + lkc); };
    auto loadB = [&](int k0) -> float4 {
        float4 v = *(const float4*)(brow_p + k0 + lkc);
        if (!rvalid) v = make_float4(0, 0, 0, 0);
        return v;
    };

    float4 ar = loadA(0), brv = loadB(0);
    As[0][lkc + 0][lm] = ar.x; As[0][lkc + 1][lm] = ar.y;
    As[0][lkc + 2][lm] = ar.z; As[0][lkc + 3][lm] = ar.w;
    Bs[0][lkc + 0][lm] = brv.x; Bs[0][lkc + 1][lm] = brv.y;
    Bs[0][lkc + 2][lm] = brv.z; Bs[0][lkc + 3][lm] = brv.w;
    __syncthreads();

    int buf = 0;
    for (int it = 0; it < NT; it++) {
        float4 an, bn;
        if (it + 1 < NT) { an = loadA((it + 1) * 16); bn = loadB((it + 1) * 16); }
        COMPUTE_TILE(buf);
        if (it + 1 < NT) {
            int nb = buf ^ 1;
            As[nb][lkc + 0][lm] = an.x; As[nb][lkc + 1][lm] = an.y;
            As[nb][lkc + 2][lm] = an.z; As[nb][lkc + 3][lm] = an.w;
            Bs[nb][lkc + 0][lm] = bn.x; Bs[nb][lkc + 1][lm] = bn.y;
            Bs[nb][lkc + 2][lm] = bn.z; Bs[nb][lkc + 3][lm] = bn.w;
            __syncthreads();
            buf = nb;
        }
    }

    #pragma unroll
    for (int i = 0; i < 4; i++) {
        int m = m0 + ty * 4 + i;
        #pragma unroll
        for (int j = 0; j < 4; j++) {
            int n = n0 + tx * 4 + j;
            if (n < NRR) g_Wr[(size_t)m * NRR + n] = acc[i][j];
        }
    }
}

// br[r] = sum_j b2[j] * rel_emb[r*256+j], j<256.  One warp per r.
__global__ void k_br(const float* __restrict__ b2, const float* __restrict__ rel_emb)
{
    int warp = threadIdx.x >> 5, lane = threadIdx.x & 31;
    int r = blockIdx.x * 8 + warp;
    if (r >= NRR) return;
    const float* rr = rel_emb + (size_t)r * DD;
    float s = 0.f;
    #pragma unroll
    for (int j = lane; j < DD; j += 32) s = fmaf(b2[j], rr[j], s);
    #pragma unroll
    for (int o = 16; o > 0; o >>= 1) s += __shfl_xor_sync(0xFFFFFFFFu, s, o);
    if (lane == 0) g_br[r] = s;
}

// ---------------------------------------------------------------------------
// Fused GEMM2: [X2 | RP] = X @ [W2 | Wr] + [b2 | br].  M=1024 K=512 N=912.
// ---------------------------------------------------------------------------
__global__ void k_gemm2f(const float* __restrict__ W2, const float* __restrict__ b2)
{
    __shared__ float As[2][16][64];
    __shared__ float Bs[2][16][64];

    int n0 = blockIdx.x * 64, m0 = blockIdx.y * 64;
    int t  = threadIdx.x;
    int tx = t & 15, ty = t >> 4;

    int lm  = t >> 2;
    int lkc = (t & 3) * 4;
    const float* arow = g_X + (size_t)(m0 + lm) * AD;

    int brr = t >> 4;
    int bcc = (t & 15) * 4;
    int bcol = n0 + bcc;

    float acc[4][4] = {};
    const int NT = AD / 16;

    auto loadA = [&](int k0) -> float4 { return *(const float4*)(arow + k0 + lkc); };
    auto loadB = [&](int k0) -> float4 {
        int k = k0 + brr;
        if (bcol < AD)      return *(const float4*)&W2[(size_t)k * AD + bcol];
        else if (bcol < NF) return *(const float4*)&g_Wr[(size_t)k * NRR + (bcol - AD)];
        else                return make_float4(0, 0, 0, 0);
    };

    float4 ar = loadA(0), brv = loadB(0);
    As[0][lkc + 0][lm] = ar.x; As[0][lkc + 1][lm] = ar.y;
    As[0][lkc + 2][lm] = ar.z; As[0][lkc + 3][lm] = ar.w;
    *(float4*)&Bs[0][brr][bcc] = brv;
    __syncthreads();

    int buf = 0;
    for (int it = 0; it < NT; it++) {
        float4 an, bn;
        if (it + 1 < NT) { an = loadA((it + 1) * 16); bn = loadB((it + 1) * 16); }
        COMPUTE_TILE(buf);
        if (it + 1 < NT) {
            int nb = buf ^ 1;
            As[nb][lkc + 0][lm] = an.x; As[nb][lkc + 1][lm] = an.y;
            As[nb][lkc + 2][lm] = an.z; As[nb][lkc + 3][lm] = an.w;
            *(float4*)&Bs[nb][brr][bcc] = bn;
            __syncthreads();
            buf = nb;
        }
    }

    #pragma unroll
    for (int i = 0; i < 4; i++) {
        int m = m0 + ty * 4 + i;
        #pragma unroll
        for (int j = 0; j < 4; j++) {
            int n = n0 + tx * 4 + j;
            if (n < AD) {
                g_X2[(size_t)m * AD + n] = acc[i][j] + b2[n];
            } else if (n < NF) {
                int r = n - AD;
                g_RP[(size_t)m * NRR + r] = acc[i][j] + g_br[r];
            }
        }
    }
}

// ---------------------------------------------------------------------------
// Scores + masked softmax + entropy. One block per batch row, 256 threads.
// 4 actions in flight per warp for MLP.
// ---------------------------------------------------------------------------
__global__ void k_scores(const int*   __restrict__ r_space,
                         const int*   __restrict__ e_space,
                         const float* __restrict__ mask,
                         const float* __restrict__ ent_emb,
                         float* __restrict__ dist,
                         float* __restrict__ entropy)
{
    int b = blockIdx.x;
    int t = threadIdx.x;
    int warp = t >> 5, lane = t & 31;

    __shared__ __align__(16) float x2b[DD];
    __shared__ float rp[NRR];
    __shared__ float sc[AN];
    __shared__ float red[8];

    x2b[t] = g_X2[(size_t)b * AD + DD + t];
    for (int i = t; i < NRR; i += 256) rp[i] = g_RP[(size_t)b * NRR + i];
    __syncthreads();

    const float4* xp = reinterpret_cast<const float4*>(x2b);
    float4 xv0 = xp[lane * 2 + 0];
    float4 xv1 = xp[lane * 2 + 1];

    const int base = b * AN;
    for (int a0 = warp * 4; a0 < AN; a0 += 32) {
        float4 v0[4], v1[4];
        #pragma unroll
        for (int j = 0; j < 4; j++) {
            int ie = e_space[base + a0 + j];
            const float4* ep = reinterpret_cast<const float4*>(ent_emb + (size_t)ie * DD);
            v0[j] = ep[lane * 2 + 0];
            v1[j] = ep[lane * 2 + 1];
        }
        float s[4];
        #pragma unroll
        for (int j = 0; j < 4; j++) {
            s[j] = v0[j].x * xv0.x + v0[j].y * xv0.y + v0[j].z * xv0.z + v0[j].w * xv0.w
                 + v1[j].x * xv1.x + v1[j].y * xv1.y + v1[j].z * xv1.z + v1[j].w * xv1.w;
        }
        #pragma unroll
        for (int o = 16; o > 0; o >>= 1) {
            #pragma unroll
            for (int j = 0; j < 4; j++) s[j] += __shfl_xor_sync(0xFFFFFFFFu, s[j], o);
        }
        if (lane < 4) {
            int a = a0 + lane;
            int ir = r_space[base + a];
            float m = mask[base + a];
            sc[a] = s[lane] + rp[ir] - (1.0f - m) * HUGEV;
        }
    }
    __syncthreads();

    float s = sc[t];

    // max reduce
    float mx = s;
    #pragma unroll
    for (int o = 16; o > 0; o >>= 1) mx = fmaxf(mx, __shfl_xor_sync(0xFFFFFFFFu, mx, o));
    if (lane == 0) red[warp] = mx;
    __syncthreads();
    if (t < 8) {
        float v = red[t];
        #pragma unroll
        for (int o = 4; o > 0; o >>= 1) v = fmaxf(v, __shfl_xor_sync(0xFFu, v, o));
        if (t == 0) red[0] = v;
    }
    __syncthreads();
    mx = red[0];

    float ex = expf(s - mx);

    float sm = ex;
    #pragma unroll
    for (int o = 16; o > 0; o >>= 1) sm += __shfl_xor_sync(0xFFFFFFFFu, sm, o);
    __syncthreads();
    if (lane == 0) red[warp] = sm;
    __syncthreads();
    if (t < 8) {
        float v = red[t];
        #pragma unroll
        for (int o = 4; o > 0; o >>= 1) v += __shfl_xor_sync(0xFFu, v, o);
        if (t == 0) red[0] = v;
    }
    __syncthreads();
    float total = red[0];

    float p = ex / total;
    dist[(size_t)b * AN + t] = p;

    float term = p * logf(fmaxf(p, 1e-20f));
    float es = term;
    #pragma unroll
    for (int o = 16; o > 0; o >>= 1) es += __shfl_xor_sync(0xFFFFFFFFu, es, o);
    __syncthreads();
    if (lane == 0) red[warp] = es;
    __syncthreads();
    if (t < 8) {
        float v = red[t];
        #pragma unroll
        for (int o = 4; o > 0; o >>= 1) v += __shfl_xor_sync(0xFFu, v, o);
        if (t == 0) entropy[b] = -v;
    }
}

// ---------------------------------------------------------------------------
extern "C" void kernel_launch(void* const* d_in, const int* in_sizes, int n_in,
                              void* d_out, int out_size)
{
    const int*   e        = (const int*)  d_in[0];
    const int*   q        = (const int*)  d_in[1];
    const float* hstate   = (const float*)d_in[2];
    const int*   r_space  = (const int*)  d_in[3];
    const int*   e_space  = (const int*)  d_in[4];
    const float* amask    = (const float*)d_in[5];
    const float* ent_emb  = (const float*)d_in[6];
    const float* rel_emb  = (const float*)d_in[7];
    const float* W1       = (const float*)d_in[8];
    const float* b1       = (const float*)d_in[9];
    const float* W2       = (const float*)d_in[10];
    const float* b2       = (const float*)d_in[11];

    float* dist    = (float*)d_out;
    float* entropy = (float*)d_out + (size_t)BB * AN;

    // Wr / br precompute (independent of gemm1 inputs)
    dim3 gw((NRR + 63) / 64, AD / 64);          // (7, 8)
    k_wr<<<gw, 256>>>(W2, rel_emb);
    k_br<<<(NRR + 7) / 8, 256>>>(b2, rel_emb);

    dim3 g1(AD / 64, BB / 64);                  // (8, 16)
    k_gemm1<<<g1, 256>>>(e, q, hstate, ent_emb, rel_emb, W1, b1);

    dim3 g2((NF + 63) / 64, BB / 64);           // (15, 16)
    k_gemm2f<<<g2, 256>>>(W2, b2);

    k_scores<<<BB, 256>>>(r_space, e_space, amask, ent_emb, dist, entropy);
}

// round 3
// speedup vs baseline: 1.9970x; 1.2848x over previous
#include <cuda_runtime.h>
#include <cuda_bf16.h>
#include <cstdint>

#define BB   1024
#define AN   256
#define DD   256
#define HD   512
#define AD   512
#define KIN  1024
#define NRR  400
#define NF   912     // AD + NRR fused N
#define HUGEV 1e31f

// Scratch (16B-aligned for float4 access)
__device__ __align__(16) float g_X [BB * AD];
__device__ __align__(16) float g_X2[BB * AD];
__device__ __align__(16) float g_RP[BB * NRR];
__device__ __align__(16) float g_Wr[AD * NRR];
__device__ __align__(16) float g_br[NRR];

// ---------------------------------------------------------------------------
// bf16 helpers
// ---------------------------------------------------------------------------
__device__ __forceinline__ uint32_t pack_bf(__nv_bfloat16 lo, __nv_bfloat16 hi) {
    __nv_bfloat162 p = __halves2bfloat162(lo, hi);
    return *reinterpret_cast<uint32_t*>(&p);
}

__device__ __forceinline__ void cvt_store4(__nv_bfloat16* ph, __nv_bfloat16* pl, float4 v) {
    float xs[4] = {v.x, v.y, v.z, v.w};
    #pragma unroll
    for (int i = 0; i < 4; i++) {
        __nv_bfloat16 h = __float2bfloat16(xs[i]);
        ph[i] = h;
        pl[i] = __float2bfloat16(xs[i] - __bfloat162float(h));
    }
}

__device__ __forceinline__ void mma16816(float c[4], const uint32_t a[4], const uint32_t b[2]) {
    asm volatile(
        "mma.sync.aligned.m16n8k16.row.col.f32.bf16.bf16.f32 "
        "{%0,%1,%2,%3}, {%4,%5,%6,%7}, {%8,%9}, {%0,%1,%2,%3};"
        : "+f"(c[0]), "+f"(c[1]), "+f"(c[2]), "+f"(c[3])
        : "r"(a[0]), "r"(a[1]), "r"(a[2]), "r"(a[3]), "r"(b[0]), "r"(b[1]));
}

// A-fragment loads (A smem layout: [row 64][k 40] bf16, row-major k-contig)
#define AFRAG_LOAD(buf, ks)                                                   \
    _Pragma("unroll")                                                         \
    for (int mt = 0; mt < 2; mt++) {                                          \
        int r0 = wm * 32 + mt * 16 + gid;                                     \
        int kk = (ks) * 16 + 2 * tig;                                         \
        ah[mt][0] = *(const uint32_t*)&Ah[buf][r0    ][kk    ];               \
        ah[mt][1] = *(const uint32_t*)&Ah[buf][r0 + 8][kk    ];               \
        ah[mt][2] = *(const uint32_t*)&Ah[buf][r0    ][kk + 8];               \
        ah[mt][3] = *(const uint32_t*)&Ah[buf][r0 + 8][kk + 8];               \
        al[mt][0] = *(const uint32_t*)&Al[buf][r0    ][kk    ];               \
        al[mt][1] = *(const uint32_t*)&Al[buf][r0 + 8][kk    ];               \
        al[mt][2] = *(const uint32_t*)&Al[buf][r0    ][kk + 8];               \
        al[mt][3] = *(const uint32_t*)&Al[buf][r0 + 8][kk + 8];               \
    }

// B fragments from [k 32][n 72] layout
#define BFRAG_KN(buf, ks)                                                     \
    _Pragma("unroll")                                                         \
    for (int nt = 0; nt < 4; nt++) {                                          \
        int c0 = wn * 32 + nt * 8 + gid;                                      \
        int kk = (ks) * 16 + 2 * tig;                                         \
        bh[nt][0] = pack_bf(Bh[buf][kk    ][c0], Bh[buf][kk + 1][c0]);        \
        bh[nt][1] = pack_bf(Bh[buf][kk + 8][c0], Bh[buf][kk + 9][c0]);        \
        bl[nt][0] = pack_bf(Bl[buf][kk    ][c0], Bl[buf][kk + 1][c0]);        \
        bl[nt][1] = pack_bf(Bl[buf][kk + 8][c0], Bl[buf][kk + 9][c0]);        \
    }

// B fragments from [n 64][k 40] layout (k-contiguous)
#define BFRAG_NK(buf, ks)                                                     \
    _Pragma("unroll")                                                         \
    for (int nt = 0; nt < 4; nt++) {                                          \
        int c0 = wn * 32 + nt * 8 + gid;                                      \
        int kk = (ks) * 16 + 2 * tig;                                         \
        bh[nt][0] = *(const uint32_t*)&Bh[buf][c0][kk    ];                   \
        bh[nt][1] = *(const uint32_t*)&Bh[buf][c0][kk + 8];                   \
        bl[nt][0] = *(const uint32_t*)&Bl[buf][c0][kk    ];                   \
        bl[nt][1] = *(const uint32_t*)&Bl[buf][c0][kk + 8];                   \
    }

#define MMA_COMPUTE(buf, BFRAG)                                               \
    _Pragma("unroll")                                                         \
    for (int ks = 0; ks < 2; ks++) {                                          \
        uint32_t ah[2][4], al[2][4], bh[4][2], bl[4][2];                      \
        AFRAG_LOAD(buf, ks);                                                  \
        BFRAG(buf, ks);                                                       \
        _Pragma("unroll")                                                     \
        for (int mt = 0; mt < 2; mt++)                                        \
            _Pragma("unroll")                                                 \
            for (int nt = 0; nt < 4; nt++) {                                  \
                mma16816(acc[mt][nt], ah[mt], bh[nt]);                        \
                mma16816(acc[mt][nt], ah[mt], bl[nt]);                        \
                mma16816(acc[mt][nt], al[mt], bh[nt]);                        \
            }                                                                 \
    }

// ---------------------------------------------------------------------------
// GEMM1: X = relu(concat(E,H,Q) @ W1 + b1).  M=1024 K=1024 N=512.
// Tiles 64x64, BK=32, 128 threads.
// ---------------------------------------------------------------------------
__global__ void __launch_bounds__(128)
k_gemm1(const int* __restrict__ e, const int* __restrict__ q,
        const float* __restrict__ hstate,
        const float* __restrict__ ent_emb,
        const float* __restrict__ rel_emb,
        const float* __restrict__ W1,
        const float* __restrict__ b1)
{
    __shared__ __nv_bfloat16 Ah[2][64][40], Al[2][64][40];
    __shared__ __nv_bfloat16 Bh[2][32][72], Bl[2][32][72];

    int t = threadIdx.x;
    int m0 = blockIdx.y * 64, n0 = blockIdx.x * 64;
    int w = t >> 5, lane = t & 31;
    int wm = w >> 1, wn = w & 1;
    int gid = lane >> 2, tig = lane & 3;

    // A load: rows t>>3 + {0,16,32,48}, k cols (t&7)*4..+3
    int arow_l = t >> 3;
    int ak4    = (t & 7) * 4;
    const float* aseg0[4]; const float* aseg1[4]; const float* aseg2[4];
    #pragma unroll
    for (int i = 0; i < 4; i++) {
        int brow = m0 + arow_l + i * 16;
        aseg0[i] = ent_emb + (size_t)e[brow] * DD;
        aseg1[i] = hstate + (size_t)brow * HD - DD;
        aseg2[i] = rel_emb + (size_t)q[brow] * DD - (DD + HD);
    }
    // B load: rows t>>4 + {0,8,16,24}, n cols (t&15)*4
    int brow_l = t >> 4;
    int bc4    = (t & 15) * 4;

    float acc[2][4][4] = {};
    const int NT = KIN / 32;

    float4 va[4], vb[4];
    auto loadT = [&](int it) {
        int k0 = it * 32;
        #pragma unroll
        for (int i = 0; i < 4; i++) {
            int gk = k0 + ak4;
            const float* p = (gk < DD) ? aseg0[i] : (gk < DD + HD) ? aseg1[i] : aseg2[i];
            va[i] = *(const float4*)(p + gk);
            vb[i] = *(const float4*)&W1[(size_t)(k0 + brow_l + i * 8) * AD + n0 + bc4];
        }
    };
    auto storeT = [&](int buf) {
        #pragma unroll
        for (int i = 0; i < 4; i++) {
            int r = arow_l + i * 16;
            cvt_store4(&Ah[buf][r][ak4], &Al[buf][r][ak4], va[i]);
            int rb = brow_l + i * 8;
            cvt_store4(&Bh[buf][rb][bc4], &Bl[buf][rb][bc4], vb[i]);
        }
    };

    loadT(0); storeT(0); __syncthreads();
    int buf = 0;
    for (int it = 0; it < NT; it++) {
        if (it + 1 < NT) loadT(it + 1);
        MMA_COMPUTE(buf, BFRAG_KN);
        if (it + 1 < NT) { storeT(buf ^ 1); __syncthreads(); buf ^= 1; }
    }

    #pragma unroll
    for (int mt = 0; mt < 2; mt++)
        #pragma unroll
        for (int nt = 0; nt < 4; nt++) {
            int r0 = m0 + wm * 32 + mt * 16 + gid;
            int c0 = n0 + wn * 32 + nt * 8 + 2 * tig;
            float2 v0 = {fmaxf(acc[mt][nt][0] + b1[c0], 0.f), fmaxf(acc[mt][nt][1] + b1[c0+1], 0.f)};
            float2 v1 = {fmaxf(acc[mt][nt][2] + b1[c0], 0.f), fmaxf(acc[mt][nt][3] + b1[c0+1], 0.f)};
            *(float2*)&g_X[(size_t)r0 * AD + c0]       = v0;
            *(float2*)&g_X[(size_t)(r0 + 8) * AD + c0] = v1;
        }
}

// ---------------------------------------------------------------------------
// Wr = W2[:, :256] @ rel_emb^T.  M=512 N=400(pad 448) K=256.
// ---------------------------------------------------------------------------
__global__ void __launch_bounds__(128)
k_wr(const float* __restrict__ W2, const float* __restrict__ rel_emb)
{
    __shared__ __nv_bfloat16 Ah[2][64][40], Al[2][64][40];
    __shared__ __nv_bfloat16 Bh[2][64][40], Bl[2][64][40];

    int t = threadIdx.x;
    int m0 = blockIdx.y * 64, n0 = blockIdx.x * 64;
    int w = t >> 5, lane = t & 31;
    int wm = w >> 1, wn = w & 1;
    int gid = lane >> 2, tig = lane & 3;

    int arow_l = t >> 3;
    int ak4    = (t & 7) * 4;

    float acc[2][4][4] = {};
    const int NT = DD / 32;

    float4 va[4], vb[4];
    auto loadT = [&](int it) {
        int k0 = it * 32;
        #pragma unroll
        for (int i = 0; i < 4; i++) {
            int r = arow_l + i * 16;
            va[i] = *(const float4*)&W2[(size_t)(m0 + r) * AD + k0 + ak4];
            int rr = n0 + r;
            vb[i] = (rr < NRR) ? *(const float4*)&rel_emb[(size_t)rr * DD + k0 + ak4]
                               : make_float4(0.f, 0.f, 0.f, 0.f);
        }
    };
    auto storeT = [&](int buf) {
        #pragma unroll
        for (int i = 0; i < 4; i++) {
            int r = arow_l + i * 16;
            cvt_store4(&Ah[buf][r][ak4], &Al[buf][r][ak4], va[i]);
            cvt_store4(&Bh[buf][r][ak4], &Bl[buf][r][ak4], vb[i]);
        }
    };

    loadT(0); storeT(0); __syncthreads();
    int buf = 0;
    for (int it = 0; it < NT; it++) {
        if (it + 1 < NT) loadT(it + 1);
        MMA_COMPUTE(buf, BFRAG_NK);
        if (it + 1 < NT) { storeT(buf ^ 1); __syncthreads(); buf ^= 1; }
    }

    #pragma unroll
    for (int mt = 0; mt < 2; mt++)
        #pragma unroll
        for (int nt = 0; nt < 4; nt++) {
            int r0 = m0 + wm * 32 + mt * 16 + gid;
            int c0 = n0 + wn * 32 + nt * 8 + 2 * tig;
            if (c0 < NRR) {
                g_Wr[(size_t)r0 * NRR + c0]       = acc[mt][nt][0];
                g_Wr[(size_t)(r0 + 8) * NRR + c0] = acc[mt][nt][2];
            }
            if (c0 + 1 < NRR) {
                g_Wr[(size_t)r0 * NRR + c0 + 1]       = acc[mt][nt][1];
                g_Wr[(size_t)(r0 + 8) * NRR + c0 + 1] = acc[mt][nt][3];
            }
        }
}

// br[r] = sum_j b2[j] * rel_emb[r*256+j]
__global__ void k_br(const float* __restrict__ b2, const float* __restrict__ rel_emb)
{
    int warp = threadIdx.x >> 5, lane = threadIdx.x & 31;
    int r = blockIdx.x * 8 + warp;
    if (r >= NRR) return;
    const float* rr = rel_emb + (size_t)r * DD;
    float s = 0.f;
    #pragma unroll
    for (int j = lane; j < DD; j += 32) s = fmaf(b2[j], rr[j], s);
    #pragma unroll
    for (int o = 16; o > 0; o >>= 1) s += __shfl_xor_sync(0xFFFFFFFFu, s, o);
    if (lane == 0) g_br[r] = s;
}

// ---------------------------------------------------------------------------
// Fused GEMM2: [X2 | RP] = X @ [W2 | Wr] + [b2 | br].  M=1024 K=512 N=912.
// ---------------------------------------------------------------------------
__global__ void __launch_bounds__(128)
k_gemm2f(const float* __restrict__ W2, const float* __restrict__ b2)
{
    __shared__ __nv_bfloat16 Ah[2][64][40], Al[2][64][40];
    __shared__ __nv_bfloat16 Bh[2][32][72], Bl[2][32][72];

    int t = threadIdx.x;
    int m0 = blockIdx.y * 64, n0 = blockIdx.x * 64;
    int w = t >> 5, lane = t & 31;
    int wm = w >> 1, wn = w & 1;
    int gid = lane >> 2, tig = lane & 3;

    int arow_l = t >> 3;
    int ak4    = (t & 7) * 4;
    int brow_l = t >> 4;
    int bc4    = (t & 15) * 4;
    int bcol   = n0 + bc4;

    float acc[2][4][4] = {};
    const int NT = AD / 32;

    float4 va[4], vb[4];
    auto loadT = [&](int it) {
        int k0 = it * 32;
        #pragma unroll
        for (int i = 0; i < 4; i++) {
            int r = arow_l + i * 16;
            va[i] = *(const float4*)&g_X[(size_t)(m0 + r) * AD + k0 + ak4];
            int k = k0 + brow_l + i * 8;
            if (bcol < AD)      vb[i] = *(const float4*)&W2[(size_t)k * AD + bcol];
            else if (bcol < NF) vb[i] = *(const float4*)&g_Wr[(size_t)k * NRR + (bcol - AD)];
            else                vb[i] = make_float4(0.f, 0.f, 0.f, 0.f);
        }
    };
    auto storeT = [&](int buf) {
        #pragma unroll
        for (int i = 0; i < 4; i++) {
            int r = arow_l + i * 16;
            cvt_store4(&Ah[buf][r][ak4], &Al[buf][r][ak4], va[i]);
            int rb = brow_l + i * 8;
            cvt_store4(&Bh[buf][rb][bc4], &Bl[buf][rb][bc4], vb[i]);
        }
    };

    loadT(0); storeT(0); __syncthreads();
    int buf = 0;
    for (int it = 0; it < NT; it++) {
        if (it + 1 < NT) loadT(it + 1);
        MMA_COMPUTE(buf, BFRAG_KN);
        if (it + 1 < NT) { storeT(buf ^ 1); __syncthreads(); buf ^= 1; }
    }

    #pragma unroll
    for (int mt = 0; mt < 2; mt++)
        #pragma unroll
        for (int nt = 0; nt < 4; nt++) {
            int r0 = m0 + wm * 32 + mt * 16 + gid;
            int c0 = n0 + wn * 32 + nt * 8 + 2 * tig;
            #pragma unroll
            for (int jj = 0; jj < 2; jj++) {
                int c = c0 + jj;
                float v0 = acc[mt][nt][jj];       // row r0
                float v1 = acc[mt][nt][2 + jj];   // row r0+8
                if (c < AD) {
                    g_X2[(size_t)r0 * AD + c]       = v0 + b2[c];
                    g_X2[(size_t)(r0 + 8) * AD + c] = v1 + b2[c];
                } else if (c < NF) {
                    int rel = c - AD;
                    float brv = g_br[rel];
                    g_RP[(size_t)r0 * NRR + rel]       = v0 + brv;
                    g_RP[(size_t)(r0 + 8) * NRR + rel] = v1 + brv;
                }
            }
        }
}

// ---------------------------------------------------------------------------
// Scores + masked softmax + entropy. One block per batch row, 256 threads.
// ---------------------------------------------------------------------------
__global__ void k_scores(const int*   __restrict__ r_space,
                         const int*   __restrict__ e_space,
                         const float* __restrict__ mask,
                         const float* __restrict__ ent_emb,
                         float* __restrict__ dist,
                         float* __restrict__ entropy)
{
    int b = blockIdx.x;
    int t = threadIdx.x;
    int warp = t >> 5, lane = t & 31;

    __shared__ __align__(16) float x2b[DD];
    __shared__ float rp[NRR];
    __shared__ float sc[AN];
    __shared__ float red[8];

    x2b[t] = g_X2[(size_t)b * AD + DD + t];
    for (int i = t; i < NRR; i += 256) rp[i] = g_RP[(size_t)b * NRR + i];
    __syncthreads();

    const float4* xp = reinterpret_cast<const float4*>(x2b);
    float4 xv0 = xp[lane * 2 + 0];
    float4 xv1 = xp[lane * 2 + 1];

    const int base = b * AN;
    for (int a0 = warp * 4; a0 < AN; a0 += 32) {
        float4 v0[4], v1[4];
        #pragma unroll
        for (int j = 0; j < 4; j++) {
            int ie = e_space[base + a0 + j];
            const float4* ep = reinterpret_cast<const float4*>(ent_emb + (size_t)ie * DD);
            v0[j] = ep[lane * 2 + 0];
            v1[j] = ep[lane * 2 + 1];
        }
        float s[4];
        #pragma unroll
        for (int j = 0; j < 4; j++) {
            s[j] = v0[j].x * xv0.x + v0[j].y * xv0.y + v0[j].z * xv0.z + v0[j].w * xv0.w
                 + v1[j].x * xv1.x + v1[j].y * xv1.y + v1[j].z * xv1.z + v1[j].w * xv1.w;
        }
        #pragma unroll
        for (int o = 16; o > 0; o >>= 1) {
            #pragma unroll
            for (int j = 0; j < 4; j++) s[j] += __shfl_xor_sync(0xFFFFFFFFu, s[j], o);
        }
        if (lane < 4) {
            int a = a0 + lane;
            int ir = r_space[base + a];
            float m = mask[base + a];
            sc[a] = s[lane] + rp[ir] - (1.0f - m) * HUGEV;
        }
    }
    __syncthreads();

    float s = sc[t];

    float mx = s;
    #pragma unroll
    for (int o = 16; o > 0; o >>= 1) mx = fmaxf(mx, __shfl_xor_sync(0xFFFFFFFFu, mx, o));
    if (lane == 0) red[warp] = mx;
    __syncthreads();
    if (t < 8) {
        float v = red[t];
        #pragma unroll
        for (int o = 4; o > 0; o >>= 1) v = fmaxf(v, __shfl_xor_sync(0xFFu, v, o));
        if (t == 0) red[0] = v;
    }
    __syncthreads();
    mx = red[0];

    float ex = expf(s - mx);

    float sm = ex;
    #pragma unroll
    for (int o = 16; o > 0; o >>= 1) sm += __shfl_xor_sync(0xFFFFFFFFu, sm, o);
    __syncthreads();
    if (lane == 0) red[warp] = sm;
    __syncthreads();
    if (t < 8) {
        float v = red[t];
        #pragma unroll
        for (int o = 4; o > 0; o >>= 1) v += __shfl_xor_sync(0xFFu, v, o);
        if (t == 0) red[0] = v;
    }
    __syncthreads();
    float total = red[0];

    float p = ex / total;
    dist[(size_t)b * AN + t] = p;

    float term = p * logf(fmaxf(p, 1e-20f));
    float es = term;
    #pragma unroll
    for (int o = 16; o > 0; o >>= 1) es += __shfl_xor_sync(0xFFFFFFFFu, es, o);
    __syncthreads();
    if (lane == 0) red[warp] = es;
    __syncthreads();
    if (t < 8) {
        float v = red[t];
        #pragma unroll
        for (int o = 4; o > 0; o >>= 1) v += __shfl_xor_sync(0xFFu, v, o);
        if (t == 0) entropy[b] = -v;
    }
}

// ---------------------------------------------------------------------------
extern "C" void kernel_launch(void* const* d_in, const int* in_sizes, int n_in,
                              void* d_out, int out_size)
{
    const int*   e        = (const int*)  d_in[0];
    const int*   q        = (const int*)  d_in[1];
    const float* hstate   = (const float*)d_in[2];
    const int*   r_space  = (const int*)  d_in[3];
    const int*   e_space  = (const int*)  d_in[4];
    const float* amask    = (const float*)d_in[5];
    const float* ent_emb  = (const float*)d_in[6];
    const float* rel_emb  = (const float*)d_in[7];
    const float* W1       = (const float*)d_in[8];
    const float* b1       = (const float*)d_in[9];
    const float* W2       = (const float*)d_in[10];
    const float* b2       = (const float*)d_in[11];

    float* dist    = (float*)d_out;
    float* entropy = (float*)d_out + (size_t)BB * AN;

    dim3 gw((NRR + 63) / 64, AD / 64);          // (7, 8)
    k_wr<<<gw, 128>>>(W2, rel_emb);
    k_br<<<(NRR + 7) / 8, 256>>>(b2, rel_emb);

    dim3 g1(AD / 64, BB / 64);                  // (8, 16)
    k_gemm1<<<g1, 128>>>(e, q, hstate, ent_emb, rel_emb, W1, b1);

    dim3 g2((NF + 63) / 64, BB / 64);           // (15, 16)
    k_gemm2f<<<g2, 128>>>(W2, b2);

    k_scores<<<BB, 256>>>(r_space, e_space, amask, ent_emb, dist, entropy);
}

// round 4
// speedup vs baseline: 2.2578x; 1.1306x over previous
#include <cuda_runtime.h>
#include <cuda_bf16.h>
#include <cstdint>

#define BB   1024
#define AN   256
#define DD   256
#define HD   512
#define AD   512
#define KIN  1024
#define NRR  400
#define NF   912
#define HUGEV 1e31f

__device__ __align__(16) float g_X [BB * AD];
__device__ __align__(16) float g_X2[BB * AD];
__device__ __align__(16) float g_RP[BB * NRR];
__device__ __align__(16) float g_Wr[AD * NRR];
__device__ __align__(16) float g_br[NRR];

// ---------------------------------------------------------------------------
__device__ __forceinline__ uint32_t sh_addr(const void* p) {
    return (uint32_t)__cvta_generic_to_shared(p);
}
__device__ __forceinline__ void ldsm_x4(uint32_t& r0, uint32_t& r1, uint32_t& r2, uint32_t& r3, uint32_t a) {
    asm volatile("ldmatrix.sync.aligned.m8n8.x4.shared.b16 {%0,%1,%2,%3}, [%4];"
                 : "=r"(r0), "=r"(r1), "=r"(r2), "=r"(r3) : "r"(a));
}
__device__ __forceinline__ void ldsm_x4_t(uint32_t& r0, uint32_t& r1, uint32_t& r2, uint32_t& r3, uint32_t a) {
    asm volatile("ldmatrix.sync.aligned.m8n8.x4.trans.shared.b16 {%0,%1,%2,%3}, [%4];"
                 : "=r"(r0), "=r"(r1), "=r"(r2), "=r"(r3) : "r"(a));
}
__device__ __forceinline__ void mma16816(float c[4], const uint32_t a[4], const uint32_t b[2]) {
    asm volatile(
        "mma.sync.aligned.m16n8k16.row.col.f32.bf16.bf16.f32 "
        "{%0,%1,%2,%3}, {%4,%5,%6,%7}, {%8,%9}, {%0,%1,%2,%3};"
        : "+f"(c[0]), "+f"(c[1]), "+f"(c[2]), "+f"(c[3])
        : "r"(a[0]), "r"(a[1]), "r"(a[2]), "r"(a[3]), "r"(b[0]), "r"(b[1]));
}
__device__ __forceinline__ uint32_t pack2(__nv_bfloat16 a, __nv_bfloat16 b) {
    __nv_bfloat162 p = __halves2bfloat162(a, b);
    return *reinterpret_cast<uint32_t*>(&p);
}
// fp32x4 -> (hi bf16 x4, lo bf16 x4), vectorized 8B stores
__device__ __forceinline__ void cvt_store4(__nv_bfloat16* ph, __nv_bfloat16* pl, float4 v) {
    float xs[4] = {v.x, v.y, v.z, v.w};
    __nv_bfloat16 h[4], l[4];
    #pragma unroll
    for (int i = 0; i < 4; i++) {
        h[i] = __float2bfloat16(xs[i]);
        l[i] = __float2bfloat16(xs[i] - __bfloat162float(h[i]));
    }
    uint2 hw = {pack2(h[0], h[1]), pack2(h[2], h[3])};
    uint2 lw = {pack2(l[0], l[1]), pack2(l[2], l[3])};
    *(uint2*)ph = hw;
    *(uint2*)pl = lw;
}

// A-plane smem: [64][40] bf16 (row-major, k-contig).  B KN: [32][72].  B NK: [64][40].
// Per-ks compute: A frag via 2x ldsm.x4, B frags via ldsm.x4(.trans), 12 mmas.
#define MMA_TILE_KN(buf)                                                      \
    _Pragma("unroll")                                                         \
    for (int ks = 0; ks < 2; ks++) {                                          \
        uint32_t ah[4], al[4], bh[4][2], bl[4][2];                            \
        ldsm_x4(ah[0], ah[1], ah[2], ah[3], aAh[buf] + ks * 32);              \
        ldsm_x4(al[0], al[1], al[2], al[3], aAl[buf] + ks * 32);              \
        _Pragma("unroll")                                                     \
        for (int p = 0; p < 2; p++) {                                         \
            uint32_t off = (uint32_t)(ks * 16 * 144 + p * 32);                \
            ldsm_x4_t(bh[2*p][0], bh[2*p][1], bh[2*p+1][0], bh[2*p+1][1], aBh[buf] + off); \
            ldsm_x4_t(bl[2*p][0], bl[2*p][1], bl[2*p+1][0], bl[2*p+1][1], aBl[buf] + off); \
        }                                                                     \
        _Pragma("unroll")                                                     \
        for (int nt = 0; nt < 4; nt++) {                                      \
            mma16816(acc[nt], ah, bh[nt]);                                    \
            mma16816(acc[nt], ah, bl[nt]);                                    \
            mma16816(acc[nt], al, bh[nt]);                                    \
        }                                                                     \
    }

#define MMA_TILE_NK(buf)                                                      \
    _Pragma("unroll")                                                         \
    for (int ks = 0; ks < 2; ks++) {                                          \
        uint32_t ah[4], al[4], bh[4][2], bl[4][2];                            \
        ldsm_x4(ah[0], ah[1], ah[2], ah[3], aAh[buf] + ks * 32);              \
        ldsm_x4(al[0], al[1], al[2], al[3], aAl[buf] + ks * 32);              \
        _Pragma("unroll")                                                     \
        for (int p = 0; p < 2; p++) {                                         \
            uint32_t off = (uint32_t)(p * 16 * 80 + ks * 32);                 \
            ldsm_x4(bh[2*p][0], bh[2*p][1], bh[2*p+1][0], bh[2*p+1][1], aBh[buf] + off); \
            ldsm_x4(bl[2*p][0], bl[2*p][1], bl[2*p+1][0], bl[2*p+1][1], aBl[buf] + off); \
        }                                                                     \
        _Pragma("unroll")                                                     \
        for (int nt = 0; nt < 4; nt++) {                                      \
            mma16816(acc[nt], ah, bh[nt]);                                    \
            mma16816(acc[nt], ah, bl[nt]);                                    \
            mma16816(acc[nt], al, bh[nt]);                                    \
        }                                                                     \
    }

// Common per-thread ids for GEMMs (256 threads, 8 warps: wm=w>>1 in [0,4), wn=w&1)
#define GEMM_IDS                                                              \
    int t = threadIdx.x;                                                      \
    int w = t >> 5, lane = t & 31;                                            \
    int wm = w >> 1, wn = w & 1;                                              \
    int gid = lane >> 2, tig = lane & 3;                                      \
    int lj = lane >> 3, lr = lane & 7;

// LDSM lane base offsets (bytes) into the smem planes
#define LDSM_A_BASE(Ah, Al)                                                   \
    uint32_t aAh[2], aAl[2];                                                  \
    {   int a_row = wm * 16 + (lj & 1) * 8 + lr;                              \
        int a_kc  = (lj >> 1) * 8;                                            \
        aAh[0] = sh_addr(&Ah[0][a_row][a_kc]);                                \
        aAh[1] = sh_addr(&Ah[1][a_row][a_kc]);                                \
        aAl[0] = sh_addr(&Al[0][a_row][a_kc]);                                \
        aAl[1] = sh_addr(&Al[1][a_row][a_kc]); }

#define LDSM_BKN_BASE(Bh, Bl)                                                 \
    uint32_t aBh[2], aBl[2];                                                  \
    {   int b_kr = (lj & 1) * 8 + lr;                                         \
        int b_nc = wn * 32 + (lj >> 1) * 8;                                   \
        aBh[0] = sh_addr(&Bh[0][b_kr][b_nc]);                                 \
        aBh[1] = sh_addr(&Bh[1][b_kr][b_nc]);                                 \
        aBl[0] = sh_addr(&Bl[0][b_kr][b_nc]);                                 \
        aBl[1] = sh_addr(&Bl[1][b_kr][b_nc]); }

#define LDSM_BNK_BASE(Bh, Bl)                                                 \
    uint32_t aBh[2], aBl[2];                                                  \
    {   int b_nr = wn * 32 + (lj >> 1) * 8 + lr;                              \
        int b_kc = (lj & 1) * 8;                                              \
        aBh[0] = sh_addr(&Bh[0][b_nr][b_kc]);                                 \
        aBh[1] = sh_addr(&Bh[1][b_nr][b_kc]);                                 \
        aBl[0] = sh_addr(&Bl[0][b_nr][b_kc]);                                 \
        aBl[1] = sh_addr(&Bl[1][b_nr][b_kc]); }

// ---------------------------------------------------------------------------
// GEMM1: X = relu(concat(E,H,Q) @ W1 + b1).  M=1024 K=1024 N=512.  BK=32.
// ---------------------------------------------------------------------------
__global__ void __launch_bounds__(256)
k_gemm1(const int* __restrict__ e, const int* __restrict__ q,
        const float* __restrict__ hstate,
        const float* __restrict__ ent_emb,
        const float* __restrict__ rel_emb,
        const float* __restrict__ W1,
        const float* __restrict__ b1)
{
    __shared__ __nv_bfloat16 Ah[2][64][40], Al[2][64][40];
    __shared__ __nv_bfloat16 Bh[2][32][72], Bl[2][32][72];

    GEMM_IDS;
    int m0 = blockIdx.y * 64, n0 = blockIdx.x * 64;

    LDSM_A_BASE(Ah, Al);
    LDSM_BKN_BASE(Bh, Bl);

    // A loads: 2 slots, rows arow + {0,32}, k cols ak4..+3
    int arow = t >> 3;
    int ak4  = (t & 7) * 4;
    const float* aseg0[2]; const float* aseg1[2]; const float* aseg2[2];
    #pragma unroll
    for (int i = 0; i < 2; i++) {
        int brow = m0 + arow + i * 32;
        aseg0[i] = ent_emb + (size_t)e[brow] * DD;
        aseg1[i] = hstate + (size_t)brow * HD - DD;
        aseg2[i] = rel_emb + (size_t)q[brow] * DD - (DD + HD);
    }
    // B loads: 2 slots, k rows brw + {0,16}, n cols bc4..+3
    int brw = t >> 4;
    int bc4 = (t & 15) * 4;

    float acc[4][4] = {};
    const int NT = KIN / 32;

    float4 va[2], vb[2];
    auto loadT = [&](int it) {
        int k0 = it * 32;
        int gk = k0 + ak4;
        #pragma unroll
        for (int i = 0; i < 2; i++) {
            const float* p = (gk < DD) ? aseg0[i] : (gk < DD + HD) ? aseg1[i] : aseg2[i];
            va[i] = *(const float4*)(p + gk);
            vb[i] = *(const float4*)&W1[(size_t)(k0 + brw + i * 16) * AD + n0 + bc4];
        }
    };
    auto storeT = [&](int buf) {
        #pragma unroll
        for (int i = 0; i < 2; i++) {
            int r = arow + i * 32;
            cvt_store4(&Ah[buf][r][ak4], &Al[buf][r][ak4], va[i]);
            int rb = brw + i * 16;
            cvt_store4(&Bh[buf][rb][bc4], &Bl[buf][rb][bc4], vb[i]);
        }
    };

    loadT(0); storeT(0); __syncthreads();
    int buf = 0;
    for (int it = 0; it < NT; it++) {
        if (it + 1 < NT) loadT(it + 1);
        MMA_TILE_KN(buf);
        if (it + 1 < NT) { storeT(buf ^ 1); __syncthreads(); buf ^= 1; }
    }

    #pragma unroll
    for (int nt = 0; nt < 4; nt++) {
        int r0 = m0 + wm * 16 + gid;
        int c0 = n0 + wn * 32 + nt * 8 + 2 * tig;
        float bb0 = b1[c0], bb1 = b1[c0 + 1];
        float2 v0 = {fmaxf(acc[nt][0] + bb0, 0.f), fmaxf(acc[nt][1] + bb1, 0.f)};
        float2 v1 = {fmaxf(acc[nt][2] + bb0, 0.f), fmaxf(acc[nt][3] + bb1, 0.f)};
        *(float2*)&g_X[(size_t)r0 * AD + c0]       = v0;
        *(float2*)&g_X[(size_t)(r0 + 8) * AD + c0] = v1;
    }
}

// ---------------------------------------------------------------------------
// Wr = W2[:, :256] @ rel_emb^T.  M=512 N=400 K=256.  B is NK (n-major).
// ---------------------------------------------------------------------------
__global__ void __launch_bounds__(256)
k_wr(const float* __restrict__ W2, const float* __restrict__ rel_emb)
{
    __shared__ __nv_bfloat16 Ah[2][64][40], Al[2][64][40];
    __shared__ __nv_bfloat16 Bh[2][64][40], Bl[2][64][40];

    GEMM_IDS;
    int m0 = blockIdx.y * 64, n0 = blockIdx.x * 64;

    LDSM_A_BASE(Ah, Al);
    LDSM_BNK_BASE(Bh, Bl);

    int arow = t >> 3;
    int ak4  = (t & 7) * 4;

    float acc[4][4] = {};
    const int NT = DD / 32;

    float4 va[2], vb[2];
    auto loadT = [&](int it) {
        int k0 = it * 32;
        #pragma unroll
        for (int i = 0; i < 2; i++) {
            int r = arow + i * 32;
            va[i] = *(const float4*)&W2[(size_t)(m0 + r) * AD + k0 + ak4];
            int rr = n0 + r;
            vb[i] = (rr < NRR) ? *(const float4*)&rel_emb[(size_t)rr * DD + k0 + ak4]
                               : make_float4(0.f, 0.f, 0.f, 0.f);
        }
    };
    auto storeT = [&](int buf) {
        #pragma unroll
        for (int i = 0; i < 2; i++) {
            int r = arow + i * 32;
            cvt_store4(&Ah[buf][r][ak4], &Al[buf][r][ak4], va[i]);
            cvt_store4(&Bh[buf][r][ak4], &Bl[buf][r][ak4], vb[i]);
        }
    };

    loadT(0); storeT(0); __syncthreads();
    int buf = 0;
    for (int it = 0; it < NT; it++) {
        if (it + 1 < NT) loadT(it + 1);
        MMA_TILE_NK(buf);
        if (it + 1 < NT) { storeT(buf ^ 1); __syncthreads(); buf ^= 1; }
    }

    #pragma unroll
    for (int nt = 0; nt < 4; nt++) {
        int r0 = m0 + wm * 16 + gid;
        int c0 = n0 + wn * 32 + nt * 8 + 2 * tig;
        if (c0 < NRR) {
            g_Wr[(size_t)r0 * NRR + c0]       = acc[nt][0];
            g_Wr[(size_t)(r0 + 8) * NRR + c0] = acc[nt][2];
        }
        if (c0 + 1 < NRR) {
            g_Wr[(size_t)r0 * NRR + c0 + 1]       = acc[nt][1];
            g_Wr[(size_t)(r0 + 8) * NRR + c0 + 1] = acc[nt][3];
        }
    }
}

// br[r] = sum_j b2[j] * rel_emb[r*256+j]
__global__ void k_br(const float* __restrict__ b2, const float* __restrict__ rel_emb)
{
    int warp = threadIdx.x >> 5, lane = threadIdx.x & 31;
    int r = blockIdx.x * 8 + warp;
    if (r >= NRR) return;
    const float* rr = rel_emb + (size_t)r * DD;
    float s = 0.f;
    #pragma unroll
    for (int j = lane; j < DD; j += 32) s = fmaf(b2[j], rr[j], s);
    #pragma unroll
    for (int o = 16; o > 0; o >>= 1) s += __shfl_xor_sync(0xFFFFFFFFu, s, o);
    if (lane == 0) g_br[r] = s;
}

// ---------------------------------------------------------------------------
// Fused GEMM2: [X2 | RP] = X @ [W2 | Wr] + [b2 | br].  M=1024 K=512 N=912.
// ---------------------------------------------------------------------------
__global__ void __launch_bounds__(256)
k_gemm2f(const float* __restrict__ W2, const float* __restrict__ b2)
{
    __shared__ __nv_bfloat16 Ah[2][64][40], Al[2][64][40];
    __shared__ __nv_bfloat16 Bh[2][32][72], Bl[2][32][72];

    GEMM_IDS;
    int m0 = blockIdx.y * 64, n0 = blockIdx.x * 64;

    LDSM_A_BASE(Ah, Al);
    LDSM_BKN_BASE(Bh, Bl);

    int arow = t >> 3;
    int ak4  = (t & 7) * 4;
    int brw  = t >> 4;
    int bc4  = (t & 15) * 4;
    int bcol = n0 + bc4;

    float acc[4][4] = {};
    const int NT = AD / 32;

    float4 va[2], vb[2];
    auto loadT = [&](int it) {
        int k0 = it * 32;
        #pragma unroll
        for (int i = 0; i < 2; i++) {
            int r = arow + i * 32;
            va[i] = *(const float4*)&g_X[(size_t)(m0 + r) * AD + k0 + ak4];
            int k = k0 + brw + i * 16;
            if (bcol < AD)      vb[i] = *(const float4*)&W2[(size_t)k * AD + bcol];
            else if (bcol < NF) vb[i] = *(const float4*)&g_Wr[(size_t)k * NRR + (bcol - AD)];
            else                vb[i] = make_float4(0.f, 0.f, 0.f, 0.f);
        }
    };
    auto storeT = [&](int buf) {
        #pragma unroll
        for (int i = 0; i < 2; i++) {
            int r = arow + i * 32;
            cvt_store4(&Ah[buf][r][ak4], &Al[buf][r][ak4], va[i]);
            int rb = brw + i * 16;
            cvt_store4(&Bh[buf][rb][bc4], &Bl[buf][rb][bc4], vb[i]);
        }
    };

    loadT(0); storeT(0); __syncthreads();
    int buf = 0;
    for (int it = 0; it < NT; it++) {
        if (it + 1 < NT) loadT(it + 1);
        MMA_TILE_KN(buf);
        if (it + 1 < NT) { storeT(buf ^ 1); __syncthreads(); buf ^= 1; }
    }

    #pragma unroll
    for (int nt = 0; nt < 4; nt++) {
        int r0 = m0 + wm * 16 + gid;
        int c0 = n0 + wn * 32 + nt * 8 + 2 * tig;
        #pragma unroll
        for (int jj = 0; jj < 2; jj++) {
            int c = c0 + jj;
            float v0 = acc[nt][jj];
            float v1 = acc[nt][2 + jj];
            if (c < AD) {
                float bc = b2[c];
                g_X2[(size_t)r0 * AD + c]       = v0 + bc;
                g_X2[(size_t)(r0 + 8) * AD + c] = v1 + bc;
            } else if (c < NF) {
                int rel = c - AD;
                float brv = g_br[rel];
                g_RP[(size_t)r0 * NRR + rel]       = v0 + brv;
                g_RP[(size_t)(r0 + 8) * NRR + rel] = v1 + brv;
            }
        }
    }
}

// ---------------------------------------------------------------------------
// Scores + masked softmax + entropy. One block per row, 256 threads,
// 8 actions in flight per warp.
// ---------------------------------------------------------------------------
__global__ void k_scores(const int*   __restrict__ r_space,
                         const int*   __restrict__ e_space,
                         const float* __restrict__ mask,
                         const float* __restrict__ ent_emb,
                         float* __restrict__ dist,
                         float* __restrict__ entropy)
{
    int b = blockIdx.x;
    int t = threadIdx.x;
    int warp = t >> 5, lane = t & 31;

    __shared__ __align__(16) float x2b[DD];
    __shared__ float rp[NRR];
    __shared__ float sc[AN];
    __shared__ float red[8];

    x2b[t] = g_X2[(size_t)b * AD + DD + t];
    for (int i = t; i < NRR; i += 256) rp[i] = g_RP[(size_t)b * NRR + i];
    __syncthreads();

    const float4* xp = reinterpret_cast<const float4*>(x2b);
    float4 xv0 = xp[lane * 2 + 0];
    float4 xv1 = xp[lane * 2 + 1];

    const int base = b * AN;
    for (int a0 = warp * 8; a0 < AN; a0 += 64) {
        int idx[8];
        #pragma unroll
        for (int j = 0; j < 8; j++) idx[j] = e_space[base + a0 + j];
        float4 v0[8], v1[8];
        #pragma unroll
        for (int j = 0; j < 8; j++) {
            const float4* ep = reinterpret_cast<const float4*>(ent_emb + (size_t)idx[j] * DD);
            v0[j] = ep[lane * 2 + 0];
            v1[j] = ep[lane * 2 + 1];
        }
        float s[8];
        #pragma unroll
        for (int j = 0; j < 8; j++) {
            s[j] = v0[j].x * xv0.x + v0[j].y * xv0.y + v0[j].z * xv0.z + v0[j].w * xv0.w
                 + v1[j].x * xv1.x + v1[j].y * xv1.y + v1[j].z * xv1.z + v1[j].w * xv1.w;
        }
        #pragma unroll
        for (int o = 16; o > 0; o >>= 1) {
            #pragma unroll
            for (int j = 0; j < 8; j++) s[j] += __shfl_xor_sync(0xFFFFFFFFu, s[j], o);
        }
        if (lane < 8) {
            int a = a0 + lane;
            int ir = r_space[base + a];
            float m = mask[base + a];
            sc[a] = s[lane] + rp[ir] - (1.0f - m) * HUGEV;
        }
    }
    __syncthreads();

    float s = sc[t];

    float mx = s;
    #pragma unroll
    for (int o = 16; o > 0; o >>= 1) mx = fmaxf(mx, __shfl_xor_sync(0xFFFFFFFFu, mx, o));
    if (lane == 0) red[warp] = mx;
    __syncthreads();
    if (t < 8) {
        float v = red[t];
        #pragma unroll
        for (int o = 4; o > 0; o >>= 1) v = fmaxf(v, __shfl_xor_sync(0xFFu, v, o));
        if (t == 0) red[0] = v;
    }
    __syncthreads();
    mx = red[0];

    float ex = expf(s - mx);

    float sm = ex;
    #pragma unroll
    for (int o = 16; o > 0; o >>= 1) sm += __shfl_xor_sync(0xFFFFFFFFu, sm, o);
    __syncthreads();
    if (lane == 0) red[warp] = sm;
    __syncthreads();
    if (t < 8) {
        float v = red[t];
        #pragma unroll
        for (int o = 4; o > 0; o >>= 1) v += __shfl_xor_sync(0xFFu, v, o);
        if (t == 0) red[0] = v;
    }
    __syncthreads();
    float total = red[0];

    float p = ex / total;
    dist[(size_t)b * AN + t] = p;

    float term = p * logf(fmaxf(p, 1e-20f));
    float es = term;
    #pragma unroll
    for (int o = 16; o > 0; o >>= 1) es += __shfl_xor_sync(0xFFFFFFFFu, es, o);
    __syncthreads();
    if (lane == 0) red[warp] = es;
    __syncthreads();
    if (t < 8) {
        float v = red[t];
        #pragma unroll
        for (int o = 4; o > 0; o >>= 1) v += __shfl_xor_sync(0xFFu, v, o);
        if (t == 0) entropy[b] = -v;
    }
}

// ---------------------------------------------------------------------------
extern "C" void kernel_launch(void* const* d_in, const int* in_sizes, int n_in,
                              void* d_out, int out_size)
{
    const int*   e        = (const int*)  d_in[0];
    const int*   q        = (const int*)  d_in[1];
    const float* hstate   = (const float*)d_in[2];
    const int*   r_space  = (const int*)  d_in[3];
    const int*   e_space  = (const int*)  d_in[4];
    const float* amask    = (const float*)d_in[5];
    const float* ent_emb  = (const float*)d_in[6];
    const float* rel_emb  = (const float*)d_in[7];
    const float* W1       = (const float*)d_in[8];
    const float* b1       = (const float*)d_in[9];
    const float* W2       = (const float*)d_in[10];
    const float* b2       = (const float*)d_in[11];

    float* dist    = (float*)d_out;
    float* entropy = (float*)d_out + (size_t)BB * AN;

    dim3 gw((NRR + 63) / 64, AD / 64);          // (7, 8)
    k_wr<<<gw, 256>>>(W2, rel_emb);
    k_br<<<(NRR + 7) / 8, 256>>>(b2, rel_emb);

    dim3 g1(AD / 64, BB / 64);                  // (8, 16)
    k_gemm1<<<g1, 256>>>(e, q, hstate, ent_emb, rel_emb, W1, b1);

    dim3 g2((NF + 63) / 64, BB / 64);           // (15, 16)
    k_gemm2f<<<g2, 256>>>(W2, b2);

    k_scores<<<BB, 256>>>(r_space, e_space, amask, ent_emb, dist, entropy);
}

// round 5
// speedup vs baseline: 3.1885x; 1.4122x over previous
#include <cuda_runtime.h>
#include <cuda_bf16.h>
#include <cstdint>

#define BB   1024
#define AN   256
#define DD   256
#define HD   512
#define AD   512
#define KIN  1024
#define NRR  400
#define NF2  656      // 256 live X2 cols + 400 relation cols
#define HUGEV 1e31f

// fp32 scratch
__device__ __align__(16) float g_X2h2[BB * DD];     // X2[:, 256:512]
__device__ __align__(16) float g_RP[BB * NRR];
__device__ __align__(16) float g_br[NRR];
// bf16 hi/lo planes
__device__ __align__(16) __nv_bfloat16 g_Ah [BB * KIN],  g_Al [BB * KIN];   // concat(E,H,Q)
__device__ __align__(16) __nv_bfloat16 g_W1h[KIN * AD],  g_W1l[KIN * AD];
__device__ __align__(16) __nv_bfloat16 g_W2h[AD * AD],   g_W2l[AD * AD];
__device__ __align__(16) __nv_bfloat16 g_Rh [NRR * DD],  g_Rl [NRR * DD];
__device__ __align__(16) __nv_bfloat16 g_Xh [BB * AD],   g_Xl [BB * AD];
__device__ __align__(16) __nv_bfloat16 g_Wrh[AD * NRR],  g_Wrl[AD * NRR];

// ---------------------------------------------------------------------------
__device__ __forceinline__ uint32_t sh_addr(const void* p) {
    return (uint32_t)__cvta_generic_to_shared(p);
}
__device__ __forceinline__ void cp16(uint32_t dst, const void* src, int sz) {
    asm volatile("cp.async.cg.shared.global [%0], [%1], 16, %2;" :: "r"(dst), "l"(src), "r"(sz));
}
__device__ __forceinline__ void cp_commit() { asm volatile("cp.async.commit_group;"); }
template<int N> __device__ __forceinline__ void cp_wait() {
    asm volatile("cp.async.wait_group %0;" :: "n"(N));
}
__device__ __forceinline__ void ldsm_x4(uint32_t& r0, uint32_t& r1, uint32_t& r2, uint32_t& r3, uint32_t a) {
    asm volatile("ldmatrix.sync.aligned.m8n8.x4.shared.b16 {%0,%1,%2,%3}, [%4];"
                 : "=r"(r0), "=r"(r1), "=r"(r2), "=r"(r3) : "r"(a));
}
__device__ __forceinline__ void ldsm_x4_t(uint32_t& r0, uint32_t& r1, uint32_t& r2, uint32_t& r3, uint32_t a) {
    asm volatile("ldmatrix.sync.aligned.m8n8.x4.trans.shared.b16 {%0,%1,%2,%3}, [%4];"
                 : "=r"(r0), "=r"(r1), "=r"(r2), "=r"(r3) : "r"(a));
}
__device__ __forceinline__ void mma16816(float c[4], const uint32_t a[4], const uint32_t b[2]) {
    asm volatile(
        "mma.sync.aligned.m16n8k16.row.col.f32.bf16.bf16.f32 "
        "{%0,%1,%2,%3}, {%4,%5,%6,%7}, {%8,%9}, {%0,%1,%2,%3};"
        : "+f"(c[0]), "+f"(c[1]), "+f"(c[2]), "+f"(c[3])
        : "r"(a[0]), "r"(a[1]), "r"(a[2]), "r"(a[3]), "r"(b[0]), "r"(b[1]));
}
__device__ __forceinline__ uint32_t pack2(__nv_bfloat16 a, __nv_bfloat16 b) {
    __nv_bfloat162 p = __halves2bfloat162(a, b);
    return *reinterpret_cast<uint32_t*>(&p);
}
__device__ __forceinline__ void split1(float x, __nv_bfloat16& h, __nv_bfloat16& l) {
    h = __float2bfloat16(x);
    l = __float2bfloat16(x - __bfloat162float(h));
}
__device__ __forceinline__ void split4(float4 v, uint2& hw, uint2& lw) {
    float xs[4] = {v.x, v.y, v.z, v.w};
    __nv_bfloat16 h[4], l[4];
    #pragma unroll
    for (int i = 0; i < 4; i++) split1(xs[i], h[i], l[i]);
    hw = {pack2(h[0], h[1]), pack2(h[2], h[3])};
    lw = {pack2(l[0], l[1]), pack2(l[2], l[3])};
}

// ---------------------------------------------------------------------------
// MMA tile macros: 64x64 tile, BK=32, 8 warps (wm in [0,4) x 16 rows, wn in
// [0,2) x 32 cols), 3-stage buffers.  A plane [64][40], B KN [32][72],
// B NK [64][40].
// ---------------------------------------------------------------------------
#define MMA_TILE_KN(buf)                                                      \
    _Pragma("unroll")                                                         \
    for (int ks = 0; ks < 2; ks++) {                                          \
        uint32_t ah[4], al[4], bh[4][2], bl[4][2];                            \
        ldsm_x4(ah[0], ah[1], ah[2], ah[3], aAh[buf] + ks * 32);              \
        ldsm_x4(al[0], al[1], al[2], al[3], aAl[buf] + ks * 32);              \
        _Pragma("unroll")                                                     \
        for (int p = 0; p < 2; p++) {                                         \
            uint32_t off = (uint32_t)(ks * 16 * 144 + p * 32);                \
            ldsm_x4_t(bh[2*p][0], bh[2*p][1], bh[2*p+1][0], bh[2*p+1][1], aBh[buf] + off); \
            ldsm_x4_t(bl[2*p][0], bl[2*p][1], bl[2*p+1][0], bl[2*p+1][1], aBl[buf] + off); \
        }                                                                     \
        _Pragma("unroll")                                                     \
        for (int nt = 0; nt < 4; nt++) {                                      \
            mma16816(acc[nt], ah, bh[nt]);                                    \
            mma16816(acc[nt], ah, bl[nt]);                                    \
            mma16816(acc[nt], al, bh[nt]);                                    \
        }                                                                     \
    }

#define MMA_TILE_NK(buf)                                                      \
    _Pragma("unroll")                                                         \
    for (int ks = 0; ks < 2; ks++) {                                          \
        uint32_t ah[4], al[4], bh[4][2], bl[4][2];                            \
        ldsm_x4(ah[0], ah[1], ah[2], ah[3], aAh[buf] + ks * 32);              \
        ldsm_x4(al[0], al[1], al[2], al[3], aAl[buf] + ks * 32);              \
        _Pragma("unroll")                                                     \
        for (int p = 0; p < 2; p++) {                                         \
            uint32_t off = (uint32_t)(p * 16 * 80 + ks * 32);                 \
            ldsm_x4(bh[2*p][0], bh[2*p][1], bh[2*p+1][0], bh[2*p+1][1], aBh[buf] + off); \
            ldsm_x4(bl[2*p][0], bl[2*p][1], bl[2*p+1][0], bl[2*p+1][1], aBl[buf] + off); \
        }                                                                     \
        _Pragma("unroll")                                                     \
        for (int nt = 0; nt < 4; nt++) {                                      \
            mma16816(acc[nt], ah, bh[nt]);                                    \
            mma16816(acc[nt], ah, bl[nt]);                                    \
            mma16816(acc[nt], al, bh[nt]);                                    \
        }                                                                     \
    }

#define GEMM_IDS                                                              \
    int t = threadIdx.x;                                                      \
    int w = t >> 5, lane = t & 31;                                            \
    int wm = w >> 1, wn = w & 1;                                              \
    int gid = lane >> 2, tig = lane & 3;                                      \
    int lj = lane >> 3, lr = lane & 7;

#define LDSM_A_BASE(Ah, Al)                                                   \
    uint32_t aAh[3], aAl[3];                                                  \
    {   int a_row = wm * 16 + (lj & 1) * 8 + lr;                              \
        int a_kc  = (lj >> 1) * 8;                                            \
        _Pragma("unroll")                                                     \
        for (int s = 0; s < 3; s++) {                                         \
            aAh[s] = sh_addr(&Ah[s][a_row][a_kc]);                            \
            aAl[s] = sh_addr(&Al[s][a_row][a_kc]); } }

#define LDSM_BKN_BASE(Bh, Bl)                                                 \
    uint32_t aBh[3], aBl[3];                                                  \
    {   int b_kr = (lj & 1) * 8 + lr;                                         \
        int b_nc = wn * 32 + (lj >> 1) * 8;                                   \
        _Pragma("unroll")                                                     \
        for (int s = 0; s < 3; s++) {                                         \
            aBh[s] = sh_addr(&Bh[s][b_kr][b_nc]);                             \
            aBl[s] = sh_addr(&Bl[s][b_kr][b_nc]); } }

#define LDSM_BNK_BASE(Bh, Bl)                                                 \
    uint32_t aBh[3], aBl[3];                                                  \
    {   int b_nr = wn * 32 + (lj >> 1) * 8 + lr;                              \
        int b_kc = (lj & 1) * 8;                                              \
        _Pragma("unroll")                                                     \
        for (int s = 0; s < 3; s++) {                                         \
            aBh[s] = sh_addr(&Bh[s][b_nr][b_kc]);                             \
            aBl[s] = sh_addr(&Bl[s][b_nr][b_kc]); } }

// ---------------------------------------------------------------------------
// k_prep: split W1/W2/rel into bf16 hi/lo planes; build gathered concat A.
// One float4 unit per thread.
// ---------------------------------------------------------------------------
#define U_A   (BB * KIN / 4)
#define U_W1  (KIN * AD / 4)
#define U_W2  (AD * AD / 4)
#define U_R   (NRR * DD / 4)
#define U_TOT (U_A + U_W1 + U_W2 + U_R)

__global__ void __launch_bounds__(256)
k_prep(const int* __restrict__ e, const int* __restrict__ q,
       const float* __restrict__ hstate,
       const float* __restrict__ ent_emb,
       const float* __restrict__ rel_emb,
       const float* __restrict__ W1, const float* __restrict__ W2)
{
    int u = blockIdx.x * 256 + threadIdx.x;
    if (u >= U_TOT) return;

    float4 v;
    __nv_bfloat16 *ph, *pl;
    size_t off;
    if (u < U_A) {
        int b  = u >> 8;
        int kc = (u & 255) * 4;
        const float* p = (kc < DD) ? ent_emb + (size_t)e[b] * DD + kc
                       : (kc < DD + HD) ? hstate + (size_t)b * HD + (kc - DD)
                       : rel_emb + (size_t)q[b] * DD + (kc - DD - HD);
        v = *(const float4*)p;
        off = (size_t)u * 4; ph = g_Ah; pl = g_Al;
    } else if (u < U_A + U_W1) {
        size_t i = (size_t)(u - U_A) * 4;
        v = *(const float4*)&W1[i];
        off = i; ph = g_W1h; pl = g_W1l;
    } else if (u < U_A + U_W1 + U_W2) {
        size_t i = (size_t)(u - U_A - U_W1) * 4;
        v = *(const float4*)&W2[i];
        off = i; ph = g_W2h; pl = g_W2l;
    } else {
        size_t i = (size_t)(u - U_A - U_W1 - U_W2) * 4;
        v = *(const float4*)&rel_emb[i];
        off = i; ph = g_Rh; pl = g_Rl;
    }
    uint2 hw, lw;
    split4(v, hw, lw);
    *(uint2*)&ph[off] = hw;
    *(uint2*)&pl[off] = lw;
}

// ---------------------------------------------------------------------------
// GEMM pipeline skeleton (3-stage cp.async).
// Per stage per thread: A planes 1 chunk each (row t>>2, col (t&3)*8),
// B KN planes 1 chunk each (row t>>3, col (t&7)*8).
// ---------------------------------------------------------------------------
#define PIPE_LOOP(NT, LOADER, MMA)                                            \
    LOADER(0, 0); cp_commit();                                                \
    LOADER(1, 1); cp_commit();                                                \
    int buf = 0;                                                              \
    for (int it = 0; it < NT; it++) {                                         \
        cp_wait<1>();                                                         \
        __syncthreads();                                                      \
        if (it + 2 < NT) { LOADER(it + 2, (it + 2) % 3); }                    \
        cp_commit();                                                          \
        MMA(buf);                                                             \
        buf = (buf + 1) % 3; buf = buf;                                       \
    }

// ---------------------------------------------------------------------------
// GEMM1: X = relu(A @ W1 + b1) -> bf16 hi/lo planes.  M=1024 K=1024 N=512.
// ---------------------------------------------------------------------------
__global__ void __launch_bounds__(256)
k_gemm1(const float* __restrict__ b1)
{
    __shared__ __nv_bfloat16 Ah[3][64][40], Al[3][64][40];
    __shared__ __nv_bfloat16 Bh[3][32][72], Bl[3][32][72];

    GEMM_IDS;
    int m0 = blockIdx.y * 64, n0 = blockIdx.x * 64;

    LDSM_A_BASE(Ah, Al);
    LDSM_BKN_BASE(Bh, Bl);

    int ar = t >> 2, ac = (t & 3) * 8;     // A chunk
    int br = t >> 3, bc = (t & 7) * 8;     // B chunk
    const __nv_bfloat16* gAh = g_Ah + (size_t)(m0 + ar) * KIN + ac;
    const __nv_bfloat16* gAl = g_Al + (size_t)(m0 + ar) * KIN + ac;
    uint32_t dAh[3], dAl[3], dBh[3], dBl[3];
    #pragma unroll
    for (int s = 0; s < 3; s++) {
        dAh[s] = sh_addr(&Ah[s][ar][ac]); dAl[s] = sh_addr(&Al[s][ar][ac]);
        dBh[s] = sh_addr(&Bh[s][br][bc]); dBl[s] = sh_addr(&Bl[s][br][bc]);
    }

    float acc[4][4] = {};
    const int NT = KIN / 32;

    #define LOAD1(it, s) {                                                    \
        int k0 = (it) * 32;                                                   \
        cp16(dAh[s], gAh + k0, 16);                                           \
        cp16(dAl[s], gAl + k0, 16);                                           \
        cp16(dBh[s], g_W1h + (size_t)(k0 + br) * AD + n0 + bc, 16);           \
        cp16(dBl[s], g_W1l + (size_t)(k0 + br) * AD + n0 + bc, 16); }

    PIPE_LOOP(NT, LOAD1, MMA_TILE_KN);
    #undef LOAD1

    #pragma unroll
    for (int nt = 0; nt < 4; nt++) {
        int r0 = m0 + wm * 16 + gid;
        int c0 = n0 + wn * 32 + nt * 8 + 2 * tig;
        float bb0 = b1[c0], bb1 = b1[c0 + 1];
        float v00 = fmaxf(acc[nt][0] + bb0, 0.f), v01 = fmaxf(acc[nt][1] + bb1, 0.f);
        float v10 = fmaxf(acc[nt][2] + bb0, 0.f), v11 = fmaxf(acc[nt][3] + bb1, 0.f);
        __nv_bfloat16 h0, l0, h1, l1;
        split1(v00, h0, l0); split1(v01, h1, l1);
        *(uint32_t*)&g_Xh[(size_t)r0 * AD + c0] = pack2(h0, h1);
        *(uint32_t*)&g_Xl[(size_t)r0 * AD + c0] = pack2(l0, l1);
        split1(v10, h0, l0); split1(v11, h1, l1);
        *(uint32_t*)&g_Xh[(size_t)(r0 + 8) * AD + c0] = pack2(h0, h1);
        *(uint32_t*)&g_Xl[(size_t)(r0 + 8) * AD + c0] = pack2(l0, l1);
    }
}

// ---------------------------------------------------------------------------
// Wr = W2[:, :256] @ rel_emb^T -> bf16 hi/lo.  M=512 N=400 K=256.
// ---------------------------------------------------------------------------
__global__ void __launch_bounds__(256)
k_wr()
{
    __shared__ __nv_bfloat16 Ah[3][64][40], Al[3][64][40];
    __shared__ __nv_bfloat16 Bh[3][64][40], Bl[3][64][40];

    GEMM_IDS;
    int m0 = blockIdx.y * 64, n0 = blockIdx.x * 64;

    LDSM_A_BASE(Ah, Al);
    LDSM_BNK_BASE(Bh, Bl);

    int ar = t >> 2, ac = (t & 3) * 8;
    int rr = n0 + ar;
    int bsz = (rr < NRR) ? 16 : 0;
    const __nv_bfloat16* gRh = g_Rh + (size_t)(rr < NRR ? rr : 0) * DD + ac;
    const __nv_bfloat16* gRl = g_Rl + (size_t)(rr < NRR ? rr : 0) * DD + ac;
    uint32_t dAh[3], dAl[3], dBh[3], dBl[3];
    #pragma unroll
    for (int s = 0; s < 3; s++) {
        dAh[s] = sh_addr(&Ah[s][ar][ac]); dAl[s] = sh_addr(&Al[s][ar][ac]);
        dBh[s] = sh_addr(&Bh[s][ar][ac]); dBl[s] = sh_addr(&Bl[s][ar][ac]);
    }

    float acc[4][4] = {};
    const int NT = DD / 32;

    #define LOADW(it, s) {                                                    \
        int k0 = (it) * 32;                                                   \
        cp16(dAh[s], g_W2h + (size_t)(m0 + ar) * AD + k0 + ac, 16);           \
        cp16(dAl[s], g_W2l + (size_t)(m0 + ar) * AD + k0 + ac, 16);           \
        cp16(dBh[s], gRh + k0, bsz);                                          \
        cp16(dBl[s], gRl + k0, bsz); }

    PIPE_LOOP(NT, LOADW, MMA_TILE_NK);
    #undef LOADW

    #pragma unroll
    for (int nt = 0; nt < 4; nt++) {
        int r0 = m0 + wm * 16 + gid;
        int c0 = n0 + wn * 32 + nt * 8 + 2 * tig;
        if (c0 < NRR) {
            __nv_bfloat16 h0, l0, h1, l1;
            split1(acc[nt][0], h0, l0); split1(acc[nt][1], h1, l1);
            *(uint32_t*)&g_Wrh[(size_t)r0 * NRR + c0] = pack2(h0, h1);
            *(uint32_t*)&g_Wrl[(size_t)r0 * NRR + c0] = pack2(l0, l1);
            split1(acc[nt][2], h0, l0); split1(acc[nt][3], h1, l1);
            *(uint32_t*)&g_Wrh[(size_t)(r0 + 8) * NRR + c0] = pack2(h0, h1);
            *(uint32_t*)&g_Wrl[(size_t)(r0 + 8) * NRR + c0] = pack2(l0, l1);
        }
    }
}

// br[r] = sum_j b2[j] * rel_emb[r*256+j]
__global__ void k_br(const float* __restrict__ b2, const float* __restrict__ rel_emb)
{
    int warp = threadIdx.x >> 5, lane = threadIdx.x & 31;
    int r = blockIdx.x * 8 + warp;
    if (r >= NRR) return;
    const float* rr = rel_emb + (size_t)r * DD;
    float s = 0.f;
    #pragma unroll
    for (int j = lane; j < DD; j += 32) s = fmaf(b2[j], rr[j], s);
    #pragma unroll
    for (int o = 16; o > 0; o >>= 1) s += __shfl_xor_sync(0xFFFFFFFFu, s, o);
    if (lane == 0) g_br[r] = s;
}

// ---------------------------------------------------------------------------
// GEMM2 (trimmed): [X2[:,256:512] | RP] = X @ [W2[:,256:512] | Wr] + bias.
// M=1024 K=512 N=656.
// ---------------------------------------------------------------------------
__global__ void __launch_bounds__(256)
k_gemm2f(const float* __restrict__ b2)
{
    __shared__ __nv_bfloat16 Ah[3][64][40], Al[3][64][40];
    __shared__ __nv_bfloat16 Bh[3][32][72], Bl[3][32][72];

    GEMM_IDS;
    int m0 = blockIdx.y * 64, n0 = blockIdx.x * 64;

    LDSM_A_BASE(Ah, Al);
    LDSM_BKN_BASE(Bh, Bl);

    int ar = t >> 2, ac = (t & 3) * 8;
    int br = t >> 3, bc = (t & 7) * 8;
    int bcol = n0 + bc;
    const __nv_bfloat16* gAh = g_Xh + (size_t)(m0 + ar) * AD + ac;
    const __nv_bfloat16* gAl = g_Xl + (size_t)(m0 + ar) * AD + ac;
    uint32_t dAh[3], dAl[3], dBh[3], dBl[3];
    #pragma unroll
    for (int s = 0; s < 3; s++) {
        dAh[s] = sh_addr(&Ah[s][ar][ac]); dAl[s] = sh_addr(&Al[s][ar][ac]);
        dBh[s] = sh_addr(&Bh[s][br][bc]); dBl[s] = sh_addr(&Bl[s][br][bc]);
    }

    float acc[4][4] = {};
    const int NT = AD / 32;

    #define LOAD2(it, s) {                                                    \
        int k0 = (it) * 32;                                                   \
        cp16(dAh[s], gAh + k0, 16);                                           \
        cp16(dAl[s], gAl + k0, 16);                                           \
        int kk = k0 + br;                                                     \
        const __nv_bfloat16 *sh_, *sl_; int sz_ = 16;                         \
        if (bcol < DD)       { sh_ = g_W2h + (size_t)kk * AD + DD + bcol;     \
                               sl_ = g_W2l + (size_t)kk * AD + DD + bcol; }   \
        else if (bcol < NF2) { sh_ = g_Wrh + (size_t)kk * NRR + (bcol - DD);  \
                               sl_ = g_Wrl + (size_t)kk * NRR + (bcol - DD); }\
        else                 { sh_ = g_W2h; sl_ = g_W2l; sz_ = 0; }           \
        cp16(dBh[s], sh_, sz_);                                               \
        cp16(dBl[s], sl_, sz_); }

    PIPE_LOOP(NT, LOAD2, MMA_TILE_KN);
    #undef LOAD2

    #pragma unroll
    for (int nt = 0; nt < 4; nt++) {
        int r0 = m0 + wm * 16 + gid;
        int c0 = n0 + wn * 32 + nt * 8 + 2 * tig;
        if (c0 < DD) {
            // true X2 columns 256+c0, 256+c0+1
            float bb0 = b2[DD + c0], bb1 = b2[DD + c0 + 1];
            float2 v0 = {acc[nt][0] + bb0, acc[nt][1] + bb1};
            float2 v1 = {acc[nt][2] + bb0, acc[nt][3] + bb1};
            *(float2*)&g_X2h2[(size_t)r0 * DD + c0]       = v0;
            *(float2*)&g_X2h2[(size_t)(r0 + 8) * DD + c0] = v1;
        } else if (c0 < NF2) {
            int rel = c0 - DD;
            float bb0 = g_br[rel], bb1 = g_br[rel + 1];
            float2 v0 = {acc[nt][0] + bb0, acc[nt][1] + bb1};
            float2 v1 = {acc[nt][2] + bb0, acc[nt][3] + bb1};
            *(float2*)&g_RP[(size_t)r0 * NRR + rel]       = v0;
            *(float2*)&g_RP[(size_t)(r0 + 8) * NRR + rel] = v1;
        }
    }
}

// ---------------------------------------------------------------------------
// Scores + masked softmax + entropy.
// ---------------------------------------------------------------------------
__global__ void k_scores(const int*   __restrict__ r_space,
                         const int*   __restrict__ e_space,
                         const float* __restrict__ mask,
                         const float* __restrict__ ent_emb,
                         float* __restrict__ dist,
                         float* __restrict__ entropy)
{
    int b = blockIdx.x;
    int t = threadIdx.x;
    int warp = t >> 5, lane = t & 31;

    __shared__ __align__(16) float x2b[DD];
    __shared__ float rp[NRR];
    __shared__ float sc[AN];
    __shared__ float red[8];

    x2b[t] = g_X2h2[(size_t)b * DD + t];
    for (int i = t; i < NRR; i += 256) rp[i] = g_RP[(size_t)b * NRR + i];
    __syncthreads();

    const float4* xp = reinterpret_cast<const float4*>(x2b);
    float4 xv0 = xp[lane * 2 + 0];
    float4 xv1 = xp[lane * 2 + 1];

    const int base = b * AN;
    for (int a0 = warp * 8; a0 < AN; a0 += 64) {
        int idx[8];
        #pragma unroll
        for (int j = 0; j < 8; j++) idx[j] = e_space[base + a0 + j];
        float4 v0[8], v1[8];
        #pragma unroll
        for (int j = 0; j < 8; j++) {
            const float4* ep = reinterpret_cast<const float4*>(ent_emb + (size_t)idx[j] * DD);
            v0[j] = ep[lane * 2 + 0];
            v1[j] = ep[lane * 2 + 1];
        }
        float s[8];
        #pragma unroll
        for (int j = 0; j < 8; j++) {
            s[j] = v0[j].x * xv0.x + v0[j].y * xv0.y + v0[j].z * xv0.z + v0[j].w * xv0.w
                 + v1[j].x * xv1.x + v1[j].y * xv1.y + v1[j].z * xv1.z + v1[j].w * xv1.w;
        }
        #pragma unroll
        for (int o = 16; o > 0; o >>= 1) {
            #pragma unroll
            for (int j = 0; j < 8; j++) s[j] += __shfl_xor_sync(0xFFFFFFFFu, s[j], o);
        }
        if (lane < 8) {
            int a = a0 + lane;
            int ir = r_space[base + a];
            float m = mask[base + a];
            sc[a] = s[lane] + rp[ir] - (1.0f - m) * HUGEV;
        }
    }
    __syncthreads();

    float s = sc[t];

    float mx = s;
    #pragma unroll
    for (int o = 16; o > 0; o >>= 1) mx = fmaxf(mx, __shfl_xor_sync(0xFFFFFFFFu, mx, o));
    if (lane == 0) red[warp] = mx;
    __syncthreads();
    if (t < 8) {
        float v = red[t];
        #pragma unroll
        for (int o = 4; o > 0; o >>= 1) v = fmaxf(v, __shfl_xor_sync(0xFFu, v, o));
        if (t == 0) red[0] = v;
    }
    __syncthreads();
    mx = red[0];

    float ex = expf(s - mx);

    float sm = ex;
    #pragma unroll
    for (int o = 16; o > 0; o >>= 1) sm += __shfl_xor_sync(0xFFFFFFFFu, sm, o);
    __syncthreads();
    if (lane == 0) red[warp] = sm;
    __syncthreads();
    if (t < 8) {
        float v = red[t];
        #pragma unroll
        for (int o = 4; o > 0; o >>= 1) v += __shfl_xor_sync(0xFFu, v, o);
        if (t == 0) red[0] = v;
    }
    __syncthreads();
    float total = red[0];

    float p = ex / total;
    dist[(size_t)b * AN + t] = p;

    float term = p * logf(fmaxf(p, 1e-20f));
    float es = term;
    #pragma unroll
    for (int o = 16; o > 0; o >>= 1) es += __shfl_xor_sync(0xFFFFFFFFu, es, o);
    __syncthreads();
    if (lane == 0) red[warp] = es;
    __syncthreads();
    if (t < 8) {
        float v = red[t];
        #pragma unroll
        for (int o = 4; o > 0; o >>= 1) v += __shfl_xor_sync(0xFFu, v, o);
        if (t == 0) entropy[b] = -v;
    }
}

// ---------------------------------------------------------------------------
extern "C" void kernel_launch(void* const* d_in, const int* in_sizes, int n_in,
                              void* d_out, int out_size)
{
    const int*   e        = (const int*)  d_in[0];
    const int*   q        = (const int*)  d_in[1];
    const float* hstate   = (const float*)d_in[2];
    const int*   r_space  = (const int*)  d_in[3];
    const int*   e_space  = (const int*)  d_in[4];
    const float* amask    = (const float*)d_in[5];
    const float* ent_emb  = (const float*)d_in[6];
    const float* rel_emb  = (const float*)d_in[7];
    const float* W1       = (const float*)d_in[8];
    const float* b1       = (const float*)d_in[9];
    const float* W2       = (const float*)d_in[10];
    const float* b2       = (const float*)d_in[11];

    float* dist    = (float*)d_out;
    float* entropy = (float*)d_out + (size_t)BB * AN;

    k_prep<<<U_TOT / 256, 256>>>(e, q, hstate, ent_emb, rel_emb, W1, W2);
    k_br<<<(NRR + 7) / 8, 256>>>(b2, rel_emb);

    dim3 gw((NRR + 63) / 64, AD / 64);          // (7, 8)
    k_wr<<<gw, 256>>>();

    dim3 g1(AD / 64, BB / 64);                  // (8, 16)
    k_gemm1<<<g1, 256>>>(b1);

    dim3 g2((NF2 + 63) / 64, BB / 64);          // (11, 16)
    k_gemm2f<<<g2, 256>>>(b2);

    k_scores<<<BB, 256>>>(r_space, e_space, amask, ent_emb, dist, entropy);
}